// round 1
// baseline (speedup 1.0000x reference)
#include <cuda_runtime.h>
#include <cuda_bf16.h>
#include <cstdint>

#define T_TOK 2048
#define D_MODEL 2048
#define D_FF 5632
#define KV_DIM 512
#define SEQ 1024
#define NHEAD 16
#define NKV 4
#define HDIM 128

// ---------------- scratch (static device globals; no allocation) ----------------
__device__ float g_h [T_TOK * D_MODEL];
__device__ float g_q [T_TOK * D_MODEL];
__device__ float g_k [T_TOK * KV_DIM];
__device__ float g_v [T_TOK * KV_DIM];
__device__ float g_o [T_TOK * D_MODEL];
__device__ float g_x1[T_TOK * D_MODEL];
__device__ float g_h2[T_TOK * D_MODEL];
__device__ float g_gate[T_TOK * D_FF];
__device__ float g_up  [T_TOK * D_FF];

// ---------------- f32x2 packed-FMA helpers ----------------
typedef unsigned long long u64;

__device__ __forceinline__ u64 pk2(float x, float y) {
    u64 r;
    asm("mov.b64 %0, {%1, %2};" : "=l"(r) : "f"(x), "f"(y));
    return r;
}
__device__ __forceinline__ void fma2(u64& d, u64 a, u64 b) {
    asm("fma.rn.f32x2 %0, %1, %2, %0;" : "+l"(d) : "l"(a), "l"(b));
}
__device__ __forceinline__ void unpk2(u64 v, float& lo, float& hi) {
    asm("mov.b64 {%0, %1}, %2;" : "=f"(lo), "=f"(hi) : "l"(v));
}

// ---------------- RMSNorm: one block per token row ----------------
__global__ void rmsnorm_kernel(const float* __restrict__ x,
                               const float* __restrict__ w,
                               float* __restrict__ out) {
    int row = blockIdx.x;
    int tid = threadIdx.x;
    const float4* xr = reinterpret_cast<const float4*>(x + (size_t)row * D_MODEL);
    const float4* wr = reinterpret_cast<const float4*>(w);
    float4* orow = reinterpret_cast<float4*>(out + (size_t)row * D_MODEL);

    float4 v0 = xr[tid];
    float4 v1 = xr[tid + 256];
    float s = v0.x*v0.x + v0.y*v0.y + v0.z*v0.z + v0.w*v0.w
            + v1.x*v1.x + v1.y*v1.y + v1.z*v1.z + v1.w*v1.w;
    #pragma unroll
    for (int off = 16; off; off >>= 1) s += __shfl_xor_sync(0xffffffffu, s, off);

    __shared__ float red[8];
    if ((tid & 31) == 0) red[tid >> 5] = s;
    __syncthreads();
    float tot = 0.f;
    #pragma unroll
    for (int i = 0; i < 8; i++) tot += red[i];
    float inv = rsqrtf(tot * (1.0f / D_MODEL) + 1e-6f);

    float4 w0 = wr[tid], w1 = wr[tid + 256];
    float4 o0, o1;
    o0.x = v0.x * inv * w0.x;  o0.y = v0.y * inv * w0.y;
    o0.z = v0.z * inv * w0.z;  o0.w = v0.w * inv * w0.w;
    o1.x = v1.x * inv * w1.x;  o1.y = v1.y * inv * w1.y;
    o1.z = v1.z * inv * w1.z;  o1.w = v1.w * inv * w1.w;
    orow[tid] = o0;
    orow[tid + 256] = o1;
}

// ---------------- dequantizing GEMM: C[T,O] = A[T,K] * (Wq*scale)[O,K]^T ----------------
// BM=BN=128, BK=32, 256 threads, 8x8 per thread via packed f32x2 FMA.
#define BM 128
#define BN 128
#define BK 32
#define LDS_M (BM + 4)

__global__ __launch_bounds__(256)
void gemm_dq(const float* __restrict__ A, const int* __restrict__ Wq,
             const float* __restrict__ Ws, int nG,
             const float* __restrict__ bias, const float* __restrict__ res,
             float* __restrict__ C, int T, int O, int K) {
    __shared__ __align__(16) float As[BK][LDS_M];
    __shared__ __align__(16) float Bs[BK][LDS_M];

    int bm = blockIdx.y * BM;
    int bn = blockIdx.x * BN;
    int tid = threadIdx.x;

    // loader mapping: 32 rows x (8 threads * float4) covers 128x32 tile in 4 passes
    int lr = tid >> 3;          // 0..31
    int lc = (tid & 7) << 2;    // 0,4,...,28

    // compute mapping: 16x16 threads, 8x8 tile each
    int tx = tid & 15, ty = tid >> 4;
    int m0 = ty << 3, n0 = tx << 3;

    float4 aF[4];
    int4   wI[4];
    float  wS[4];
    int nt = K / BK;

    // initial tile load (k0 = 0)
    #pragma unroll
    for (int p = 0; p < 4; p++) {
        int ar = bm + lr + p * 32;
        int wr = bn + lr + p * 32;
        aF[p] = *reinterpret_cast<const float4*>(A + (size_t)ar * K + lc);
        wI[p] = *reinterpret_cast<const int4*>(Wq + (size_t)wr * K + lc);
        wS[p] = Ws[wr * nG];
    }

    u64 acc[8][4];
    #pragma unroll
    for (int i = 0; i < 8; i++)
        #pragma unroll
        for (int j = 0; j < 4; j++) acc[i][j] = 0ull;

    for (int t = 0; t < nt; t++) {
        // store current tile to smem (dequantize W here)
        #pragma unroll
        for (int p = 0; p < 4; p++) {
            int r = lr + p * 32;
            As[lc + 0][r] = aF[p].x;  As[lc + 1][r] = aF[p].y;
            As[lc + 2][r] = aF[p].z;  As[lc + 3][r] = aF[p].w;
            float sc = wS[p];
            Bs[lc + 0][r] = (float)wI[p].x * sc;
            Bs[lc + 1][r] = (float)wI[p].y * sc;
            Bs[lc + 2][r] = (float)wI[p].z * sc;
            Bs[lc + 3][r] = (float)wI[p].w * sc;
        }
        __syncthreads();

        // prefetch next tile into registers (hides DRAM latency behind compute)
        if (t + 1 < nt) {
            int k0 = (t + 1) * BK;
            #pragma unroll
            for (int p = 0; p < 4; p++) {
                int ar = bm + lr + p * 32;
                int wr = bn + lr + p * 32;
                aF[p] = *reinterpret_cast<const float4*>(A + (size_t)ar * K + k0 + lc);
                wI[p] = *reinterpret_cast<const int4*>(Wq + (size_t)wr * K + k0 + lc);
                wS[p] = Ws[wr * nG + (k0 >> 6)];
            }
        }

        // compute
        #pragma unroll
        for (int kk = 0; kk < BK; kk++) {
            float4 a01 = *reinterpret_cast<const float4*>(&As[kk][m0]);
            float4 a23 = *reinterpret_cast<const float4*>(&As[kk][m0 + 4]);
            const u64* bp = reinterpret_cast<const u64*>(&Bs[kk][n0]);
            u64 b0 = bp[0], b1 = bp[1], b2_ = bp[2], b3 = bp[3];
            float af[8] = {a01.x, a01.y, a01.z, a01.w, a23.x, a23.y, a23.z, a23.w};
            #pragma unroll
            for (int i = 0; i < 8; i++) {
                u64 ad = pk2(af[i], af[i]);
                fma2(acc[i][0], ad, b0);
                fma2(acc[i][1], ad, b1);
                fma2(acc[i][2], ad, b2_);
                fma2(acc[i][3], ad, b3);
            }
        }
        __syncthreads();
    }

    // epilogue: optional bias (per output col) + optional residual (same shape as C)
    #pragma unroll
    for (int i = 0; i < 8; i++) {
        int row = bm + m0 + i;
        #pragma unroll
        for (int j = 0; j < 4; j++) {
            float lo, hi;
            unpk2(acc[i][j], lo, hi);
            int c0 = bn + n0 + 2 * j;
            int c1 = c0 + 1;
            if (bias) { lo += bias[c0]; hi += bias[c1]; }
            if (res) {
                lo += res[(size_t)row * O + c0];
                hi += res[(size_t)row * O + c1];
            }
            C[(size_t)row * O + c0] = lo;
            C[(size_t)row * O + c1] = hi;
        }
    }
}

// ---------------- RoPE (in-place, layout [b,s,h,d]) ----------------
__global__ void rope_kernel(float* __restrict__ X, int heads, const int* __restrict__ offp) {
    int idx = blockIdx.x * blockDim.x + threadIdx.x;
    int total = T_TOK * heads * 64;
    if (idx >= total) return;
    int j = idx & 63;
    int rest = idx >> 6;
    int h = rest % heads;
    int t = rest / heads;         // t = b*SEQ + s
    int s = t & (SEQ - 1);
    float pos = (float)(s + *offp);
    // inv = theta^(-2j/128), theta = 1e6
    float inv = exp2f(-(float)j * (2.0f / 128.0f) * 19.931568569324174f);
    float ang = pos * inv;
    float c, sn;
    sincosf(ang, &sn, &c);
    float* p = X + (size_t)t * (heads * HDIM) + h * HDIM + j;
    float x1 = p[0], x2 = p[64];
    p[0]  = x1 * c - x2 * sn;
    p[64] = x2 * c + x1 * sn;
}

// ---------------- causal GQA attention: 1 warp handles 4 consecutive queries ----------------
__global__ void attn_kernel(const float* __restrict__ Q, const float* __restrict__ K,
                            const float* __restrict__ V, float* __restrict__ Out) {
    int warp = threadIdx.x >> 5, lane = threadIdx.x & 31;
    int s0 = (blockIdx.x * 4 + warp) * 4;
    int h = blockIdx.y, b = blockIdx.z;
    int kh = h >> 2;           // H/KVH = 4
    int d0 = lane << 2;

    size_t qbase = ((size_t)(b * SEQ + s0)) * D_MODEL + h * HDIM + d0;
    float4 qv[4];
    #pragma unroll
    for (int i = 0; i < 4; i++)
        qv[i] = *reinterpret_cast<const float4*>(Q + qbase + (size_t)i * D_MODEL);

    float m[4], l[4];
    float4 acc[4];
    #pragma unroll
    for (int i = 0; i < 4; i++) {
        m[i] = -1e30f; l[i] = 0.f;
        acc[i] = make_float4(0.f, 0.f, 0.f, 0.f);
    }
    const float scale = 0.08838834764831843f;   // 1/sqrt(128)
    size_t kvbase = ((size_t)(b * SEQ)) * KV_DIM + kh * HDIM + d0;
    int tmax = s0 + 3;

    for (int t = 0; t <= tmax; t++) {
        float4 kv = *reinterpret_cast<const float4*>(K + kvbase + (size_t)t * KV_DIM);
        float d[4];
        #pragma unroll
        for (int i = 0; i < 4; i++)
            d[i] = qv[i].x * kv.x + qv[i].y * kv.y + qv[i].z * kv.z + qv[i].w * kv.w;
        #pragma unroll
        for (int off = 16; off; off >>= 1) {
            #pragma unroll
            for (int i = 0; i < 4; i++) d[i] += __shfl_xor_sync(0xffffffffu, d[i], off);
        }
        float4 vv = *reinterpret_cast<const float4*>(V + kvbase + (size_t)t * KV_DIM);
        #pragma unroll
        for (int i = 0; i < 4; i++) {
            if (t <= s0 + i) {
                float sc = d[i] * scale;
                if (sc <= m[i]) {
                    float p = __expf(sc - m[i]);
                    l[i] += p;
                    acc[i].x += p * vv.x; acc[i].y += p * vv.y;
                    acc[i].z += p * vv.z; acc[i].w += p * vv.w;
                } else {
                    float c = __expf(m[i] - sc);
                    m[i] = sc;
                    l[i] = l[i] * c + 1.f;
                    acc[i].x = acc[i].x * c + vv.x; acc[i].y = acc[i].y * c + vv.y;
                    acc[i].z = acc[i].z * c + vv.z; acc[i].w = acc[i].w * c + vv.w;
                }
            }
        }
    }
    #pragma unroll
    for (int i = 0; i < 4; i++) {
        float inv = 1.f / l[i];
        float4 r = make_float4(acc[i].x * inv, acc[i].y * inv, acc[i].z * inv, acc[i].w * inv);
        *reinterpret_cast<float4*>(Out + qbase + (size_t)i * D_MODEL) = r;
    }
}

// ---------------- silu(gate) * up, in-place into gate ----------------
__global__ void silu_mul_kernel(float* __restrict__ gate, const float* __restrict__ up, int n) {
    int i = blockIdx.x * blockDim.x + threadIdx.x;
    if (i < n) {
        float g = gate[i];
        float u = up[i];
        gate[i] = (g / (1.f + __expf(-g))) * u;
    }
}

// ---------------- orchestration ----------------
extern "C" void kernel_launch(void* const* d_in, const int* in_sizes, int n_in,
                              void* d_out, int out_size) {
    (void)in_sizes; (void)n_in; (void)out_size;
    const float* x       = (const float*)d_in[0];
    const int*   wq_q    = (const int*)  d_in[1];
    const float* wq_s    = (const float*)d_in[2];
    const float* bq      = (const float*)d_in[3];
    const int*   wk_q    = (const int*)  d_in[4];
    const float* wk_s    = (const float*)d_in[5];
    const float* bk      = (const float*)d_in[6];
    const int*   wv_q    = (const int*)  d_in[7];
    const float* wv_s    = (const float*)d_in[8];
    const float* bv      = (const float*)d_in[9];
    const int*   wo_q    = (const int*)  d_in[10];
    const float* wo_s    = (const float*)d_in[11];
    const int*   gate_q  = (const int*)  d_in[12];
    const float* gate_s  = (const float*)d_in[13];
    const int*   up_q    = (const int*)  d_in[14];
    const float* up_s    = (const float*)d_in[15];
    const int*   down_q  = (const int*)  d_in[16];
    const float* down_s  = (const float*)d_in[17];
    const float* w_in_ln = (const float*)d_in[18];
    const float* w_post_ln = (const float*)d_in[19];
    const int*   offset  = (const int*)  d_in[20];
    float* out = (float*)d_out;

    float *h, *q, *k, *v, *o, *x1, *h2, *gate, *up;
    cudaGetSymbolAddress((void**)&h,   g_h);
    cudaGetSymbolAddress((void**)&q,   g_q);
    cudaGetSymbolAddress((void**)&k,   g_k);
    cudaGetSymbolAddress((void**)&v,   g_v);
    cudaGetSymbolAddress((void**)&o,   g_o);
    cudaGetSymbolAddress((void**)&x1,  g_x1);
    cudaGetSymbolAddress((void**)&h2,  g_h2);
    cudaGetSymbolAddress((void**)&gate, g_gate);
    cudaGetSymbolAddress((void**)&up,  g_up);

    // 1) input rmsnorm
    rmsnorm_kernel<<<T_TOK, 256>>>(x, w_in_ln, h);

    // 2) q/k/v projections (dequant GEMM + bias)
    gemm_dq<<<dim3(D_MODEL / BN, T_TOK / BM), 256>>>(h, wq_q, wq_s, D_MODEL / 64, bq, nullptr,
                                                     q, T_TOK, D_MODEL, D_MODEL);
    gemm_dq<<<dim3(KV_DIM / BN, T_TOK / BM), 256>>>(h, wk_q, wk_s, D_MODEL / 64, bk, nullptr,
                                                    k, T_TOK, KV_DIM, D_MODEL);
    gemm_dq<<<dim3(KV_DIM / BN, T_TOK / BM), 256>>>(h, wv_q, wv_s, D_MODEL / 64, bv, nullptr,
                                                    v, T_TOK, KV_DIM, D_MODEL);

    // 3) RoPE on q and k
    rope_kernel<<<(T_TOK * NHEAD * 64 + 255) / 256, 256>>>(q, NHEAD, offset);
    rope_kernel<<<(T_TOK * NKV * 64 + 255) / 256, 256>>>(k, NKV, offset);

    // 4) causal GQA attention
    attn_kernel<<<dim3(SEQ / 16, NHEAD, 2), 128>>>(q, k, v, o);

    // 5) o-projection + residual add (x1 = x + o @ Wo^T)
    gemm_dq<<<dim3(D_MODEL / BN, T_TOK / BM), 256>>>(o, wo_q, wo_s, D_MODEL / 64, nullptr, x,
                                                     x1, T_TOK, D_MODEL, D_MODEL);

    // 6) post-attention rmsnorm
    rmsnorm_kernel<<<T_TOK, 256>>>(x1, w_post_ln, h2);

    // 7) MLP: gate & up projections
    gemm_dq<<<dim3(D_FF / BN, T_TOK / BM), 256>>>(h2, gate_q, gate_s, D_MODEL / 64, nullptr, nullptr,
                                                  gate, T_TOK, D_FF, D_MODEL);
    gemm_dq<<<dim3(D_FF / BN, T_TOK / BM), 256>>>(h2, up_q, up_s, D_MODEL / 64, nullptr, nullptr,
                                                  up, T_TOK, D_FF, D_MODEL);

    // 8) silu(gate) * up
    silu_mul_kernel<<<(T_TOK * D_FF + 255) / 256, 256>>>(gate, up, T_TOK * D_FF);

    // 9) down projection + final residual (out = x1 + mlp)
    gemm_dq<<<dim3(D_MODEL / BN, T_TOK / BM), 256>>>(gate, down_q, down_s, D_FF / 64, nullptr, x1,
                                                     out, T_TOK, D_MODEL, D_FF);
}

// round 3
// speedup vs baseline: 2.5664x; 2.5664x over previous
#include <cuda_runtime.h>
#include <cuda_bf16.h>
#include <cstdint>

#define T_TOK 2048
#define D_MODEL 2048
#define D_FF 5632
#define KV_DIM 512
#define SEQ 1024
#define NHEAD 16
#define NKV 4
#define HDIM 128

// ---------------- scratch (static device globals; no allocation) ----------------
__device__ float g_h [T_TOK * D_MODEL];
__device__ float g_q [T_TOK * D_MODEL];
__device__ float g_k [T_TOK * KV_DIM];
__device__ float g_v [T_TOK * KV_DIM];
__device__ float g_o [T_TOK * D_MODEL];
__device__ float g_x1[T_TOK * D_MODEL];
__device__ float g_h2[T_TOK * D_MODEL];
__device__ float g_gate[T_TOK * D_FF];
__device__ float g_up  [T_TOK * D_FF];

// bf16 weights (int8 values are EXACT in bf16; scales applied in GEMM per group)
#define W_TOTAL 45088768
#define OFF_WQ   0
#define OFF_WK   4194304
#define OFF_WV   5242880
#define OFF_WO   6291456
#define OFF_GATE 10485760
#define OFF_UP   22020096
#define OFF_DOWN 33554432
__device__ __nv_bfloat16 g_wbf[W_TOTAL];

// activation hi/lo split buffers (sized for largest GEMM input: T x D_FF)
__device__ __nv_bfloat16 g_ahi[T_TOK * D_FF];
__device__ __nv_bfloat16 g_alo[T_TOK * D_FF];

// ---------------- helpers ----------------
__device__ __forceinline__ uint32_t smem_u32(const void* p) {
    uint32_t a;
    asm("{ .reg .u64 t; cvta.to.shared.u64 t, %1; cvt.u32.u64 %0, t; }" : "=r"(a) : "l"(p));
    return a;
}
__device__ __forceinline__ uint32_t sw128(uint32_t off) { return off ^ ((off >> 3) & 0x70u); }

__device__ __forceinline__ uint32_t f2bf_bits(float f) {
    uint32_t u = __float_as_uint(f);
    return (u + 0x7fffu + ((u >> 16) & 1u)) >> 16;
}
__device__ __forceinline__ float bf2f(uint32_t b) { return __uint_as_float(b << 16); }

#define CP16(saddr, gptr) \
    asm volatile("cp.async.cg.shared.global [%0], [%1], 16;" :: "r"(saddr), "l"(gptr))
#define CP4(saddr, gptr) \
    asm volatile("cp.async.ca.shared.global [%0], [%1], 4;" :: "r"(saddr), "l"(gptr))
#define CP_COMMIT() asm volatile("cp.async.commit_group;" ::: "memory")
#define CP_WAIT(n)  asm volatile("cp.async.wait_group %0;" :: "n"(n) : "memory")

#define LDSM_X4(r, addr) \
    asm volatile("ldmatrix.sync.aligned.m8n8.x4.shared.b16 {%0,%1,%2,%3}, [%4];" \
        : "=r"((r)[0]), "=r"((r)[1]), "=r"((r)[2]), "=r"((r)[3]) : "r"(addr))

__device__ __forceinline__ void mma_bf16(float* c, const uint32_t* a, uint32_t b0, uint32_t b1) {
    asm volatile("mma.sync.aligned.m16n8k16.row.col.f32.bf16.bf16.f32 "
        "{%0,%1,%2,%3}, {%4,%5,%6,%7}, {%8,%9}, {%0,%1,%2,%3};"
        : "+f"(c[0]), "+f"(c[1]), "+f"(c[2]), "+f"(c[3])
        : "r"(a[0]), "r"(a[1]), "r"(a[2]), "r"(a[3]), "r"(b0), "r"(b1));
}

// ---------------- weight convert: int32 -> bf16 (exact) ----------------
__global__ void w2bf_kernel(const int* __restrict__ q, __nv_bfloat16* __restrict__ w, int n4) {
    int idx = blockIdx.x * blockDim.x + threadIdx.x;
    if (idx >= n4) return;
    int4 v = *reinterpret_cast<const int4*>(q + idx * 4);
    uint32_t b0 = f2bf_bits((float)v.x), b1 = f2bf_bits((float)v.y);
    uint32_t b2 = f2bf_bits((float)v.z), b3 = f2bf_bits((float)v.w);
    *reinterpret_cast<uint2*>(w + idx * 4) = make_uint2(b0 | (b1 << 16), b2 | (b3 << 16));
}

// ---------------- activation split: fp32 -> bf16 hi + bf16 lo ----------------
__global__ void split_kernel(const float* __restrict__ A, __nv_bfloat16* __restrict__ hi,
                             __nv_bfloat16* __restrict__ lo, int n4) {
    int idx = blockIdx.x * blockDim.x + threadIdx.x;
    if (idx >= n4) return;
    float4 f = *reinterpret_cast<const float4*>(A + idx * 4);
    float ff[4] = {f.x, f.y, f.z, f.w};
    uint32_t hb[4], lb[4];
    #pragma unroll
    for (int i = 0; i < 4; i++) {
        hb[i] = f2bf_bits(ff[i]);
        lb[i] = f2bf_bits(ff[i] - bf2f(hb[i]));
    }
    *reinterpret_cast<uint2*>(hi + idx * 4) = make_uint2(hb[0] | (hb[1] << 16), hb[2] | (hb[3] << 16));
    *reinterpret_cast<uint2*>(lo + idx * 4) = make_uint2(lb[0] | (lb[1] << 16), lb[2] | (lb[3] << 16));
}

// ---------------- tensor-core GEMM via mma.sync ----------------
// C[T,O] = (Ahi+Alo)[T,K] @ (Wbf * groupscale)[O,K]^T (+bias)(+res)
// BM=BN=128, BK=64 (= scale group), 512 threads (16 warps, 4x4, 32x32 warp tile).
#define STAGE_BYTES 49664
#define S_AHI 0
#define S_ALO 16384
#define S_W   32768
#define S_SC  49152
#define GSMEM_BYTES (2 * STAGE_BYTES + 1024)

__global__ void __launch_bounds__(512, 1)
gemm_mma(const __nv_bfloat16* __restrict__ Ahi, const __nv_bfloat16* __restrict__ Alo,
         const __nv_bfloat16* __restrict__ W, const float* __restrict__ Ws,
         const float* __restrict__ bias, const float* __restrict__ res,
         float* __restrict__ C, int O, int K) {
    extern __shared__ char dsm[];
    uint32_t sbraw = smem_u32(dsm);
    uint32_t sb = (sbraw + 1023u) & ~1023u;
    char* bp = dsm + (sb - sbraw);

    int tid = threadIdx.x, lane = tid & 31, wid = tid >> 5;
    int wm = wid >> 2, wn = wid & 3;
    int mb = blockIdx.y * 128, nb = blockIdx.x * 128;
    int nc = K >> 6;          // number of k-tiles = number of scale groups

    // load mapping: v = tid + it*512 over 1024 16B-vectors per 128x64 bf16 tile
    int lrow = tid >> 3;              // used with it offset
    (void)lrow;

    float acc[2][4][4];
    #pragma unroll
    for (int a = 0; a < 2; a++)
        #pragma unroll
        for (int b = 0; b < 4; b++)
            #pragma unroll
            for (int d = 0; d < 4; d++) acc[a][b][d] = 0.f;

    // ---- prologue: load tile 0 ----
    {
        uint32_t s0 = sb;
        #pragma unroll
        for (int it = 0; it < 2; it++) {
            int v = tid + it * 512;
            int row = v >> 3, kc = (v & 7) << 3;
            uint32_t so = sw128((uint32_t)(row * 128 + kc * 2));
            const __nv_bfloat16* ga = Ahi + (size_t)(mb + row) * K + kc;
            const __nv_bfloat16* gl = Alo + (size_t)(mb + row) * K + kc;
            const __nv_bfloat16* gw = W + (size_t)(nb + row) * K + kc;
            CP16(s0 + S_AHI + so, ga);
            CP16(s0 + S_ALO + so, gl);
            CP16(s0 + S_W + so, gw);
        }
        if (tid < 128) CP4(s0 + S_SC + tid * 4, Ws + (size_t)(nb + tid) * nc);
        CP_COMMIT();
    }

    for (int c = 0; c < nc; c++) {
        uint32_t scur = sb + (uint32_t)(c & 1) * STAGE_BYTES;
        // issue next tile
        if (c + 1 < nc) {
            uint32_t snxt = sb + (uint32_t)((c + 1) & 1) * STAGE_BYTES;
            int k0 = (c + 1) << 6;
            #pragma unroll
            for (int it = 0; it < 2; it++) {
                int v = tid + it * 512;
                int row = v >> 3, kc = (v & 7) << 3;
                uint32_t so = sw128((uint32_t)(row * 128 + kc * 2));
                const __nv_bfloat16* ga = Ahi + (size_t)(mb + row) * K + k0 + kc;
                const __nv_bfloat16* gl = Alo + (size_t)(mb + row) * K + k0 + kc;
                const __nv_bfloat16* gw = W + (size_t)(nb + row) * K + k0 + kc;
                CP16(snxt + S_AHI + so, ga);
                CP16(snxt + S_ALO + so, gl);
                CP16(snxt + S_W + so, gw);
            }
            if (tid < 128) CP4(snxt + S_SC + tid * 4, Ws + (size_t)(nb + tid) * nc + (c + 1));
            CP_COMMIT();
            CP_WAIT(1);
        } else {
            CP_WAIT(0);
        }
        __syncthreads();

        // ---- compute this tile: 2 passes (a_hi, a_lo) into group accumulator ----
        float gacc[2][4][4];
        #pragma unroll
        for (int a = 0; a < 2; a++)
            #pragma unroll
            for (int b = 0; b < 4; b++)
                #pragma unroll
                for (int d = 0; d < 4; d++) gacc[a][b][d] = 0.f;

        #pragma unroll
        for (int pass = 0; pass < 2; pass++) {
            uint32_t abase = scur + (pass ? S_ALO : S_AHI);
            #pragma unroll
            for (int ks = 0; ks < 4; ks++) {
                int kh = ks << 4;
                uint32_t afr[2][4], bfr[2][4];
                #pragma unroll
                for (int mf = 0; mf < 2; mf++) {
                    int row = wm * 32 + mf * 16 + (lane & 7) + ((lane >> 3) & 1) * 8;
                    int kk = kh + ((lane >> 4) << 3);
                    LDSM_X4(afr[mf], abase + sw128((uint32_t)(row * 128 + kk * 2)));
                }
                #pragma unroll
                for (int np = 0; np < 2; np++) {
                    int n = wn * 32 + np * 16 + (lane & 7) + ((lane >> 4) << 3);
                    int kk = kh + ((lane >> 3) & 1) * 8;
                    LDSM_X4(bfr[np], scur + S_W + sw128((uint32_t)(n * 128 + kk * 2)));
                }
                #pragma unroll
                for (int mf = 0; mf < 2; mf++)
                    #pragma unroll
                    for (int nf = 0; nf < 4; nf++)
                        mma_bf16(gacc[mf][nf], afr[mf], bfr[nf >> 1][(nf & 1) * 2],
                                 bfr[nf >> 1][(nf & 1) * 2 + 1]);
            }
        }

        // ---- fold group accumulator with per-(col,group) scale ----
        const float* sp = reinterpret_cast<const float*>(bp + (c & 1) * STAGE_BYTES + S_SC);
        #pragma unroll
        for (int nf = 0; nf < 4; nf++) {
            int cc = wn * 32 + nf * 8 + (lane & 3) * 2;
            float s0 = sp[cc], s1 = sp[cc + 1];
            #pragma unroll
            for (int mf = 0; mf < 2; mf++) {
                acc[mf][nf][0] += gacc[mf][nf][0] * s0;
                acc[mf][nf][1] += gacc[mf][nf][1] * s1;
                acc[mf][nf][2] += gacc[mf][nf][2] * s0;
                acc[mf][nf][3] += gacc[mf][nf][3] * s1;
            }
        }
        __syncthreads();
    }

    // ---- epilogue ----
    #pragma unroll
    for (int mf = 0; mf < 2; mf++) {
        int row = mb + wm * 32 + mf * 16 + (lane >> 2);
        #pragma unroll
        for (int nf = 0; nf < 4; nf++) {
            int col = nb + wn * 32 + nf * 8 + (lane & 3) * 2;
            float v0 = acc[mf][nf][0], v1 = acc[mf][nf][1];
            float v2 = acc[mf][nf][2], v3 = acc[mf][nf][3];
            if (bias) {
                float b0 = bias[col], b1 = bias[col + 1];
                v0 += b0; v1 += b1; v2 += b0; v3 += b1;
            }
            size_t o0 = (size_t)row * O + col;
            size_t o1 = (size_t)(row + 8) * O + col;
            if (res) {
                float2 r0 = *reinterpret_cast<const float2*>(res + o0);
                float2 r1 = *reinterpret_cast<const float2*>(res + o1);
                v0 += r0.x; v1 += r0.y; v2 += r1.x; v3 += r1.y;
            }
            *reinterpret_cast<float2*>(C + o0) = make_float2(v0, v1);
            *reinterpret_cast<float2*>(C + o1) = make_float2(v2, v3);
        }
    }
}

// ---------------- RMSNorm ----------------
__global__ void rmsnorm_kernel(const float* __restrict__ x,
                               const float* __restrict__ w,
                               float* __restrict__ out) {
    int row = blockIdx.x;
    int tid = threadIdx.x;
    const float4* xr = reinterpret_cast<const float4*>(x + (size_t)row * D_MODEL);
    const float4* wr = reinterpret_cast<const float4*>(w);
    float4* orow = reinterpret_cast<float4*>(out + (size_t)row * D_MODEL);

    float4 v0 = xr[tid];
    float4 v1 = xr[tid + 256];
    float s = v0.x*v0.x + v0.y*v0.y + v0.z*v0.z + v0.w*v0.w
            + v1.x*v1.x + v1.y*v1.y + v1.z*v1.z + v1.w*v1.w;
    #pragma unroll
    for (int off = 16; off; off >>= 1) s += __shfl_xor_sync(0xffffffffu, s, off);

    __shared__ float red[8];
    if ((tid & 31) == 0) red[tid >> 5] = s;
    __syncthreads();
    float tot = 0.f;
    #pragma unroll
    for (int i = 0; i < 8; i++) tot += red[i];
    float inv = rsqrtf(tot * (1.0f / D_MODEL) + 1e-6f);

    float4 w0 = wr[tid], w1 = wr[tid + 256];
    float4 o0, o1;
    o0.x = v0.x * inv * w0.x;  o0.y = v0.y * inv * w0.y;
    o0.z = v0.z * inv * w0.z;  o0.w = v0.w * inv * w0.w;
    o1.x = v1.x * inv * w1.x;  o1.y = v1.y * inv * w1.y;
    o1.z = v1.z * inv * w1.z;  o1.w = v1.w * inv * w1.w;
    orow[tid] = o0;
    orow[tid + 256] = o1;
}

// ---------------- RoPE ----------------
__global__ void rope_kernel(float* __restrict__ X, int heads, const int* __restrict__ offp) {
    int idx = blockIdx.x * blockDim.x + threadIdx.x;
    int total = T_TOK * heads * 64;
    if (idx >= total) return;
    int j = idx & 63;
    int rest = idx >> 6;
    int h = rest % heads;
    int t = rest / heads;
    int s = t & (SEQ - 1);
    float pos = (float)(s + *offp);
    float inv = exp2f(-(float)j * (2.0f / 128.0f) * 19.931568569324174f);
    float ang = pos * inv;
    float c, sn;
    sincosf(ang, &sn, &c);
    float* p = X + (size_t)t * (heads * HDIM) + h * HDIM + j;
    float x1 = p[0], x2 = p[64];
    p[0]  = x1 * c - x2 * sn;
    p[64] = x2 * c + x1 * sn;
}

// ---------------- causal GQA attention ----------------
__global__ void attn_kernel(const float* __restrict__ Q, const float* __restrict__ K,
                            const float* __restrict__ V, float* __restrict__ Out) {
    int warp = threadIdx.x >> 5, lane = threadIdx.x & 31;
    int s0 = (blockIdx.x * 4 + warp) * 4;
    int h = blockIdx.y, b = blockIdx.z;
    int kh = h >> 2;
    int d0 = lane << 2;

    size_t qbase = ((size_t)(b * SEQ + s0)) * D_MODEL + h * HDIM + d0;
    float4 qv[4];
    #pragma unroll
    for (int i = 0; i < 4; i++)
        qv[i] = *reinterpret_cast<const float4*>(Q + qbase + (size_t)i * D_MODEL);

    float m[4], l[4];
    float4 acc[4];
    #pragma unroll
    for (int i = 0; i < 4; i++) {
        m[i] = -1e30f; l[i] = 0.f;
        acc[i] = make_float4(0.f, 0.f, 0.f, 0.f);
    }
    const float scale = 0.08838834764831843f;
    size_t kvbase = ((size_t)(b * SEQ)) * KV_DIM + kh * HDIM + d0;
    int tmax = s0 + 3;

    for (int t = 0; t <= tmax; t++) {
        float4 kv = *reinterpret_cast<const float4*>(K + kvbase + (size_t)t * KV_DIM);
        float d[4];
        #pragma unroll
        for (int i = 0; i < 4; i++)
            d[i] = qv[i].x * kv.x + qv[i].y * kv.y + qv[i].z * kv.z + qv[i].w * kv.w;
        #pragma unroll
        for (int off = 16; off; off >>= 1) {
            #pragma unroll
            for (int i = 0; i < 4; i++) d[i] += __shfl_xor_sync(0xffffffffu, d[i], off);
        }
        float4 vv = *reinterpret_cast<const float4*>(V + kvbase + (size_t)t * KV_DIM);
        #pragma unroll
        for (int i = 0; i < 4; i++) {
            if (t <= s0 + i) {
                float sc = d[i] * scale;
                if (sc <= m[i]) {
                    float p = __expf(sc - m[i]);
                    l[i] += p;
                    acc[i].x += p * vv.x; acc[i].y += p * vv.y;
                    acc[i].z += p * vv.z; acc[i].w += p * vv.w;
                } else {
                    float c = __expf(m[i] - sc);
                    m[i] = sc;
                    l[i] = l[i] * c + 1.f;
                    acc[i].x = acc[i].x * c + vv.x; acc[i].y = acc[i].y * c + vv.y;
                    acc[i].z = acc[i].z * c + vv.z; acc[i].w = acc[i].w * c + vv.w;
                }
            }
        }
    }
    #pragma unroll
    for (int i = 0; i < 4; i++) {
        float inv = 1.f / l[i];
        float4 r = make_float4(acc[i].x * inv, acc[i].y * inv, acc[i].z * inv, acc[i].w * inv);
        *reinterpret_cast<float4*>(Out + qbase + (size_t)i * D_MODEL) = r;
    }
}

// ---------------- silu(gate) * up ----------------
__global__ void silu_mul_kernel(float* __restrict__ gate, const float* __restrict__ up, int n) {
    int i = blockIdx.x * blockDim.x + threadIdx.x;
    if (i < n) {
        float g = gate[i];
        float u = up[i];
        gate[i] = (g / (1.f + __expf(-g))) * u;
    }
}

// ---------------- orchestration ----------------
extern "C" void kernel_launch(void* const* d_in, const int* in_sizes, int n_in,
                              void* d_out, int out_size) {
    (void)in_sizes; (void)n_in; (void)out_size;
    const float* x       = (const float*)d_in[0];
    const int*   wq_q    = (const int*)  d_in[1];
    const float* wq_s    = (const float*)d_in[2];
    const float* bq      = (const float*)d_in[3];
    const int*   wk_q    = (const int*)  d_in[4];
    const float* wk_s    = (const float*)d_in[5];
    const float* bk      = (const float*)d_in[6];
    const int*   wv_q    = (const int*)  d_in[7];
    const float* wv_s    = (const float*)d_in[8];
    const float* bv      = (const float*)d_in[9];
    const int*   wo_q    = (const int*)  d_in[10];
    const float* wo_s    = (const float*)d_in[11];
    const int*   gate_q  = (const int*)  d_in[12];
    const float* gate_s  = (const float*)d_in[13];
    const int*   up_q    = (const int*)  d_in[14];
    const float* up_s    = (const float*)d_in[15];
    const int*   down_q  = (const int*)  d_in[16];
    const float* down_s  = (const float*)d_in[17];
    const float* w_in_ln = (const float*)d_in[18];
    const float* w_post_ln = (const float*)d_in[19];
    const int*   offset  = (const int*)  d_in[20];
    float* out = (float*)d_out;

    float *h, *q, *k, *v, *o, *x1, *h2, *gate, *up;
    __nv_bfloat16 *wbf, *ahi, *alo;
    cudaGetSymbolAddress((void**)&h,   g_h);
    cudaGetSymbolAddress((void**)&q,   g_q);
    cudaGetSymbolAddress((void**)&k,   g_k);
    cudaGetSymbolAddress((void**)&v,   g_v);
    cudaGetSymbolAddress((void**)&o,   g_o);
    cudaGetSymbolAddress((void**)&x1,  g_x1);
    cudaGetSymbolAddress((void**)&h2,  g_h2);
    cudaGetSymbolAddress((void**)&gate, g_gate);
    cudaGetSymbolAddress((void**)&up,  g_up);
    cudaGetSymbolAddress((void**)&wbf, g_wbf);
    cudaGetSymbolAddress((void**)&ahi, g_ahi);
    cudaGetSymbolAddress((void**)&alo, g_alo);

    cudaFuncSetAttribute(gemm_mma, cudaFuncAttributeMaxDynamicSharedMemorySize, GSMEM_BYTES);

    // 0) weights -> bf16 (exact, no scale)
    {
        struct { const int* q; long off; int n; } ws[7] = {
            {wq_q,   OFF_WQ,   D_MODEL * D_MODEL},
            {wk_q,   OFF_WK,   KV_DIM * D_MODEL},
            {wv_q,   OFF_WV,   KV_DIM * D_MODEL},
            {wo_q,   OFF_WO,   D_MODEL * D_MODEL},
            {gate_q, OFF_GATE, D_FF * D_MODEL},
            {up_q,   OFF_UP,   D_FF * D_MODEL},
            {down_q, OFF_DOWN, D_MODEL * D_FF},
        };
        for (int i = 0; i < 7; i++) {
            int n4 = ws[i].n / 4;
            w2bf_kernel<<<(n4 + 255) / 256, 256>>>(ws[i].q, wbf + ws[i].off, n4);
        }
    }

    const int nD4 = T_TOK * D_MODEL / 4;
    const int nF4 = T_TOK * D_FF / 4;

    // 1) input rmsnorm -> h; split
    rmsnorm_kernel<<<T_TOK, 256>>>(x, w_in_ln, h);
    split_kernel<<<(nD4 + 255) / 256, 256>>>(h, ahi, alo, nD4);

    // 2) q/k/v projections
    gemm_mma<<<dim3(D_MODEL/128, T_TOK/128), 512, GSMEM_BYTES>>>(
        ahi, alo, wbf + OFF_WQ, wq_s, bq, nullptr, q, D_MODEL, D_MODEL);
    gemm_mma<<<dim3(KV_DIM/128, T_TOK/128), 512, GSMEM_BYTES>>>(
        ahi, alo, wbf + OFF_WK, wk_s, bk, nullptr, k, KV_DIM, D_MODEL);
    gemm_mma<<<dim3(KV_DIM/128, T_TOK/128), 512, GSMEM_BYTES>>>(
        ahi, alo, wbf + OFF_WV, wv_s, bv, nullptr, v, KV_DIM, D_MODEL);

    // 3) RoPE
    rope_kernel<<<(T_TOK * NHEAD * 64 + 255) / 256, 256>>>(q, NHEAD, offset);
    rope_kernel<<<(T_TOK * NKV * 64 + 255) / 256, 256>>>(k, NKV, offset);

    // 4) attention
    attn_kernel<<<dim3(SEQ / 16, NHEAD, 2), 128>>>(q, k, v, o);

    // 5) o-projection + residual
    split_kernel<<<(nD4 + 255) / 256, 256>>>(o, ahi, alo, nD4);
    gemm_mma<<<dim3(D_MODEL/128, T_TOK/128), 512, GSMEM_BYTES>>>(
        ahi, alo, wbf + OFF_WO, wo_s, nullptr, x, x1, D_MODEL, D_MODEL);

    // 6) post rmsnorm -> h2; split
    rmsnorm_kernel<<<T_TOK, 256>>>(x1, w_post_ln, h2);
    split_kernel<<<(nD4 + 255) / 256, 256>>>(h2, ahi, alo, nD4);

    // 7) gate & up
    gemm_mma<<<dim3(D_FF/128, T_TOK/128), 512, GSMEM_BYTES>>>(
        ahi, alo, wbf + OFF_GATE, gate_s, nullptr, nullptr, gate, D_FF, D_MODEL);
    gemm_mma<<<dim3(D_FF/128, T_TOK/128), 512, GSMEM_BYTES>>>(
        ahi, alo, wbf + OFF_UP, up_s, nullptr, nullptr, up, D_FF, D_MODEL);

    // 8) silu * up
    silu_mul_kernel<<<(T_TOK * D_FF + 255) / 256, 256>>>(gate, up, T_TOK * D_FF);

    // 9) down + residual -> out
    split_kernel<<<(nF4 + 255) / 256, 256>>>(gate, ahi, alo, nF4);
    gemm_mma<<<dim3(D_MODEL/128, T_TOK/128), 512, GSMEM_BYTES>>>(
        ahi, alo, wbf + OFF_DOWN, down_s, nullptr, x1, out, D_MODEL, D_FF);
}

// round 4
// speedup vs baseline: 3.5087x; 1.3672x over previous
#include <cuda_runtime.h>
#include <cuda_bf16.h>
#include <cstdint>

#define T_TOK 2048
#define D_MODEL 2048
#define D_FF 5632
#define KV_DIM 512
#define SEQ 1024
#define NHEAD 16
#define NKV 4
#define HDIM 128

// ---------------- scratch (static device globals; no allocation) ----------------
__device__ float g_qkv[T_TOK * 3072];     // fused q|k|v rows
__device__ float g_x1 [T_TOK * D_MODEL];
__device__ float g_gu [T_TOK * 11264];    // fused gate|up
__device__ __nv_bfloat16 g_ahi[T_TOK * D_FF];
__device__ __nv_bfloat16 g_alo[T_TOK * D_FF];

// bf16 weights (int8 values EXACT in bf16; group scales applied in GEMM)
#define W_TOTAL 45088768
#define OFF_QKV  0            // 3072 x 2048  (wq | wk | wv rows)
#define OFF_WK   4194304
#define OFF_WV   5242880
#define OFF_WO   6291456      // 2048 x 2048
#define OFF_GU   10485760     // 11264 x 2048 (gate | up rows)
#define OFF_UP   22020096
#define OFF_DOWN 33554432     // 2048 x 5632
__device__ __nv_bfloat16 g_wbf[W_TOTAL];
__device__ float g_scales[458752];        // qkv scales [3072*32] @0, gu scales [11264*32] @98304
__device__ float g_bias[3072];            // bq|bk|bv

// ---------------- helpers ----------------
__device__ __forceinline__ uint32_t smem_u32(const void* p) {
    uint32_t a;
    asm("{ .reg .u64 t; cvta.to.shared.u64 t, %1; cvt.u32.u64 %0, t; }" : "=r"(a) : "l"(p));
    return a;
}
__device__ __forceinline__ uint32_t sw128(uint32_t off) { return off ^ ((off >> 3) & 0x70u); }
__device__ __forceinline__ uint32_t f2bf_bits(float f) {
    uint32_t u = __float_as_uint(f);
    return (u + 0x7fffu + ((u >> 16) & 1u)) >> 16;
}
__device__ __forceinline__ float bf2f(uint32_t b) { return __uint_as_float(b << 16); }

#define CP16(saddr, gptr) \
    asm volatile("cp.async.cg.shared.global [%0], [%1], 16;" :: "r"(saddr), "l"(gptr))
#define CP4(saddr, gptr) \
    asm volatile("cp.async.ca.shared.global [%0], [%1], 4;" :: "r"(saddr), "l"(gptr))
#define CP_COMMIT() asm volatile("cp.async.commit_group;" ::: "memory")
#define CP_WAIT(n)  asm volatile("cp.async.wait_group %0;" :: "n"(n) : "memory")

#define LDSM_X4(r, addr) \
    asm volatile("ldmatrix.sync.aligned.m8n8.x4.shared.b16 {%0,%1,%2,%3}, [%4];" \
        : "=r"((r)[0]), "=r"((r)[1]), "=r"((r)[2]), "=r"((r)[3]) : "r"(addr))

__device__ __forceinline__ void mma_bf16(float* c, const uint32_t* a, uint32_t b0, uint32_t b1) {
    asm volatile("mma.sync.aligned.m16n8k16.row.col.f32.bf16.bf16.f32 "
        "{%0,%1,%2,%3}, {%4,%5,%6,%7}, {%8,%9}, {%0,%1,%2,%3};"
        : "+f"(c[0]), "+f"(c[1]), "+f"(c[2]), "+f"(c[3])
        : "r"(a[0]), "r"(a[1]), "r"(a[2]), "r"(a[3]), "r"(b0), "r"(b1));
}

// ---------------- weight convert: int32 -> bf16 (exact) ----------------
__global__ void w2bf_kernel(const int* __restrict__ q, __nv_bfloat16* __restrict__ w, int n4) {
    int idx = blockIdx.x * blockDim.x + threadIdx.x;
    if (idx >= n4) return;
    int4 v = *reinterpret_cast<const int4*>(q + idx * 4);
    uint32_t b0 = f2bf_bits((float)v.x), b1 = f2bf_bits((float)v.y);
    uint32_t b2 = f2bf_bits((float)v.z), b3 = f2bf_bits((float)v.w);
    *reinterpret_cast<uint2*>(w + idx * 4) = make_uint2(b0 | (b1 << 16), b2 | (b3 << 16));
}

// ---------------- RMSNorm fused with hi/lo split ----------------
__global__ void rmsnorm_split(const float* __restrict__ x, const float* __restrict__ w,
                              __nv_bfloat16* __restrict__ hi, __nv_bfloat16* __restrict__ lo) {
    int row = blockIdx.x, tid = threadIdx.x;
    const float4* xr = reinterpret_cast<const float4*>(x + (size_t)row * D_MODEL);
    const float4* wr = reinterpret_cast<const float4*>(w);

    float4 v0 = xr[tid], v1 = xr[tid + 256];
    float s = v0.x*v0.x + v0.y*v0.y + v0.z*v0.z + v0.w*v0.w
            + v1.x*v1.x + v1.y*v1.y + v1.z*v1.z + v1.w*v1.w;
    #pragma unroll
    for (int off = 16; off; off >>= 1) s += __shfl_xor_sync(0xffffffffu, s, off);
    __shared__ float red[8];
    if ((tid & 31) == 0) red[tid >> 5] = s;
    __syncthreads();
    float tot = 0.f;
    #pragma unroll
    for (int i = 0; i < 8; i++) tot += red[i];
    float inv = rsqrtf(tot * (1.0f / D_MODEL) + 1e-6f);

    float4 w0 = wr[tid], w1 = wr[tid + 256];
    float vals[8] = { v0.x*inv*w0.x, v0.y*inv*w0.y, v0.z*inv*w0.z, v0.w*inv*w0.w,
                      v1.x*inv*w1.x, v1.y*inv*w1.y, v1.z*inv*w1.z, v1.w*inv*w1.w };
    uint32_t hb[8], lb[8];
    #pragma unroll
    for (int i = 0; i < 8; i++) {
        hb[i] = f2bf_bits(vals[i]);
        lb[i] = f2bf_bits(vals[i] - bf2f(hb[i]));
    }
    uint2* hp = reinterpret_cast<uint2*>(hi + (size_t)row * D_MODEL);
    uint2* lp = reinterpret_cast<uint2*>(lo + (size_t)row * D_MODEL);
    hp[tid]       = make_uint2(hb[0] | (hb[1] << 16), hb[2] | (hb[3] << 16));
    hp[tid + 256] = make_uint2(hb[4] | (hb[5] << 16), hb[6] | (hb[7] << 16));
    lp[tid]       = make_uint2(lb[0] | (lb[1] << 16), lb[2] | (lb[3] << 16));
    lp[tid + 256] = make_uint2(lb[4] | (lb[5] << 16), lb[6] | (lb[7] << 16));
}

// ---------------- tensor-core GEMM via mma.sync ----------------
// C[T,O] = (Ahi+Alo)[T,K] @ (Wbf * groupscale)[O,K]^T (+bias)(+res)
#define STAGE_BYTES 49664
#define S_AHI 0
#define S_ALO 16384
#define S_W   32768
#define S_SC  49152
#define GSMEM_BYTES (2 * STAGE_BYTES + 1024)

__global__ void __launch_bounds__(512, 1)
gemm_mma(const __nv_bfloat16* __restrict__ Ahi, const __nv_bfloat16* __restrict__ Alo,
         const __nv_bfloat16* __restrict__ W, const float* __restrict__ Ws,
         const float* __restrict__ bias, const float* __restrict__ res,
         float* __restrict__ C, int O, int K) {
    extern __shared__ char dsm[];
    uint32_t sbraw = smem_u32(dsm);
    uint32_t sb = (sbraw + 1023u) & ~1023u;
    char* bp = dsm + (sb - sbraw);

    int tid = threadIdx.x, lane = tid & 31, wid = tid >> 5;
    int wm = wid >> 2, wn = wid & 3;
    int mb = blockIdx.y * 128, nb = blockIdx.x * 128;
    int nc = K >> 6;

    float acc[2][4][4];
    #pragma unroll
    for (int a = 0; a < 2; a++)
        #pragma unroll
        for (int b = 0; b < 4; b++)
            #pragma unroll
            for (int d = 0; d < 4; d++) acc[a][b][d] = 0.f;

    {
        uint32_t s0 = sb;
        #pragma unroll
        for (int it = 0; it < 2; it++) {
            int v = tid + it * 512;
            int row = v >> 3, kc = (v & 7) << 3;
            uint32_t so = sw128((uint32_t)(row * 128 + kc * 2));
            CP16(s0 + S_AHI + so, Ahi + (size_t)(mb + row) * K + kc);
            CP16(s0 + S_ALO + so, Alo + (size_t)(mb + row) * K + kc);
            CP16(s0 + S_W + so,   W   + (size_t)(nb + row) * K + kc);
        }
        if (tid < 128) CP4(s0 + S_SC + tid * 4, Ws + (size_t)(nb + tid) * nc);
        CP_COMMIT();
    }

    for (int c = 0; c < nc; c++) {
        uint32_t scur = sb + (uint32_t)(c & 1) * STAGE_BYTES;
        if (c + 1 < nc) {
            uint32_t snxt = sb + (uint32_t)((c + 1) & 1) * STAGE_BYTES;
            int k0 = (c + 1) << 6;
            #pragma unroll
            for (int it = 0; it < 2; it++) {
                int v = tid + it * 512;
                int row = v >> 3, kc = (v & 7) << 3;
                uint32_t so = sw128((uint32_t)(row * 128 + kc * 2));
                CP16(snxt + S_AHI + so, Ahi + (size_t)(mb + row) * K + k0 + kc);
                CP16(snxt + S_ALO + so, Alo + (size_t)(mb + row) * K + k0 + kc);
                CP16(snxt + S_W + so,   W   + (size_t)(nb + row) * K + k0 + kc);
            }
            if (tid < 128) CP4(snxt + S_SC + tid * 4, Ws + (size_t)(nb + tid) * nc + (c + 1));
            CP_COMMIT();
            CP_WAIT(1);
        } else {
            CP_WAIT(0);
        }
        __syncthreads();

        float gacc[2][4][4];
        #pragma unroll
        for (int a = 0; a < 2; a++)
            #pragma unroll
            for (int b = 0; b < 4; b++)
                #pragma unroll
                for (int d = 0; d < 4; d++) gacc[a][b][d] = 0.f;

        #pragma unroll
        for (int ks = 0; ks < 4; ks++) {
            int kh = ks << 4;
            uint32_t ah[2][4], al[2][4], bfr[2][4];
            #pragma unroll
            for (int mf = 0; mf < 2; mf++) {
                int row = wm * 32 + mf * 16 + (lane & 7) + ((lane >> 3) & 1) * 8;
                int kk = kh + ((lane >> 4) << 3);
                uint32_t so = sw128((uint32_t)(row * 128 + kk * 2));
                LDSM_X4(ah[mf], scur + S_AHI + so);
                LDSM_X4(al[mf], scur + S_ALO + so);
            }
            #pragma unroll
            for (int np = 0; np < 2; np++) {
                int n = wn * 32 + np * 16 + (lane & 7) + ((lane >> 4) << 3);
                int kk = kh + ((lane >> 3) & 1) * 8;
                LDSM_X4(bfr[np], scur + S_W + sw128((uint32_t)(n * 128 + kk * 2)));
            }
            #pragma unroll
            for (int mf = 0; mf < 2; mf++)
                #pragma unroll
                for (int nf = 0; nf < 4; nf++) {
                    uint32_t b0 = bfr[nf >> 1][(nf & 1) * 2], b1 = bfr[nf >> 1][(nf & 1) * 2 + 1];
                    mma_bf16(gacc[mf][nf], ah[mf], b0, b1);
                    mma_bf16(gacc[mf][nf], al[mf], b0, b1);
                }
        }

        const float* sp = reinterpret_cast<const float*>(bp + (c & 1) * STAGE_BYTES + S_SC);
        #pragma unroll
        for (int nf = 0; nf < 4; nf++) {
            int cc = wn * 32 + nf * 8 + (lane & 3) * 2;
            float s0 = sp[cc], s1 = sp[cc + 1];
            #pragma unroll
            for (int mf = 0; mf < 2; mf++) {
                acc[mf][nf][0] += gacc[mf][nf][0] * s0;
                acc[mf][nf][1] += gacc[mf][nf][1] * s1;
                acc[mf][nf][2] += gacc[mf][nf][2] * s0;
                acc[mf][nf][3] += gacc[mf][nf][3] * s1;
            }
        }
        __syncthreads();
    }

    #pragma unroll
    for (int mf = 0; mf < 2; mf++) {
        int row = mb + wm * 32 + mf * 16 + (lane >> 2);
        #pragma unroll
        for (int nf = 0; nf < 4; nf++) {
            int col = nb + wn * 32 + nf * 8 + (lane & 3) * 2;
            float v0 = acc[mf][nf][0], v1 = acc[mf][nf][1];
            float v2 = acc[mf][nf][2], v3 = acc[mf][nf][3];
            if (bias) {
                float b0 = bias[col], b1 = bias[col + 1];
                v0 += b0; v1 += b1; v2 += b0; v3 += b1;
            }
            size_t o0 = (size_t)row * O + col;
            size_t o1 = (size_t)(row + 8) * O + col;
            if (res) {
                float2 r0 = *reinterpret_cast<const float2*>(res + o0);
                float2 r1 = *reinterpret_cast<const float2*>(res + o1);
                v0 += r0.x; v1 += r0.y; v2 += r1.x; v3 += r1.y;
            }
            *reinterpret_cast<float2*>(C + o0) = make_float2(v0, v1);
            *reinterpret_cast<float2*>(C + o1) = make_float2(v2, v3);
        }
    }
}

// ---------------- RoPE on fused qkv buffer ----------------
__global__ void rope2_kernel(float* __restrict__ X, int heads, int colbase,
                             const int* __restrict__ offp) {
    int idx = blockIdx.x * blockDim.x + threadIdx.x;
    int total = T_TOK * heads * 64;
    if (idx >= total) return;
    int j = idx & 63;
    int rest = idx >> 6;
    int h = rest % heads;
    int t = rest / heads;
    int s = t & (SEQ - 1);
    float pos = (float)(s + *offp);
    float inv = exp2f(-(float)j * (2.0f / 128.0f) * 19.931568569324174f);
    float ang = pos * inv;
    float c, sn;
    sincosf(ang, &sn, &c);
    float* p = X + (size_t)t * 3072 + colbase + h * HDIM + j;
    float x1 = p[0], x2 = p[64];
    p[0]  = x1 * c - x2 * sn;
    p[64] = x2 * c + x1 * sn;
}

// ---------------- smem-tiled flash attention (fp32), writes bf16 hi/lo ----------------
// block: 256 thr (8 warps), 64 queries, one (b,h). smem: Q 32K, K^T 16K, V 16K.
#define ASMEM_BYTES 65536

__global__ void __launch_bounds__(256)
attn_tiled(const float* __restrict__ qkv, __nv_bfloat16* __restrict__ Ohi,
           __nv_bfloat16* __restrict__ Olo) {
    extern __shared__ float asmf[];
    float* q_s = asmf;               // [64][128]
    float* kT  = asmf + 64 * 128;    // [128][32]
    float* v_s = kT + 128 * 32;      // [32][128]

    int tid = threadIdx.x, warp = tid >> 5, lane = tid & 31;
    int Qb = ((int)gridDim.x - 1 - (int)blockIdx.x) * 64;   // heavy blocks first
    int h = blockIdx.y, b = blockIdx.z, kh = h >> 2;
    const float scale = 0.08838834764831843f;

    for (int i = tid; i < 64 * 32; i += 256) {
        int row = i >> 5, c4 = (i & 31) << 2;
        float4 qf = *reinterpret_cast<const float4*>(
            qkv + (size_t)(b * SEQ + Qb + row) * 3072 + h * 128 + c4);
        qf.x *= scale; qf.y *= scale; qf.z *= scale; qf.w *= scale;
        *reinterpret_cast<float4*>(q_s + row * 128 + c4) = qf;
    }

    float m[8], l[8], o[8][4];
    #pragma unroll
    for (int i = 0; i < 8; i++) {
        m[i] = -1e30f; l[i] = 0.f;
        o[i][0] = o[i][1] = o[i][2] = o[i][3] = 0.f;
    }
    int q0 = Qb + warp * 8;
    int nt = (Qb >> 5) + 2;

    for (int t = 0; t < nt; t++) {
        int kbase = t << 5;
        __syncthreads();
        {
            int key = tid & 31, dch = tid >> 5;
            const float* kg = qkv + (size_t)(b * SEQ + kbase + key) * 3072 + 2048 + kh * 128 + dch * 16;
            const float* vg = kg + 512;
            #pragma unroll
            for (int j = 0; j < 4; j++) {
                float4 kf = *reinterpret_cast<const float4*>(kg + j * 4);
                int d0 = dch * 16 + j * 4;
                kT[(d0 + 0) * 32 + key] = kf.x;
                kT[(d0 + 1) * 32 + key] = kf.y;
                kT[(d0 + 2) * 32 + key] = kf.z;
                kT[(d0 + 3) * 32 + key] = kf.w;
                *reinterpret_cast<float4*>(v_s + key * 128 + d0) =
                    *reinterpret_cast<const float4*>(vg + j * 4);
            }
        }
        __syncthreads();

        if (kbase <= q0 + 7) {
            float s[8];
            #pragma unroll
            for (int i = 0; i < 8; i++) s[i] = 0.f;
            #pragma unroll 4
            for (int d = 0; d < 128; d += 4) {
                float k0v = kT[d * 32 + lane],       k1v = kT[(d + 1) * 32 + lane];
                float k2v = kT[(d + 2) * 32 + lane], k3v = kT[(d + 3) * 32 + lane];
                const float* qrow = q_s + warp * 8 * 128 + d;
                #pragma unroll
                for (int qi = 0; qi < 8; qi++) {
                    float4 qf = *reinterpret_cast<const float4*>(qrow + qi * 128);
                    s[qi] += qf.x * k0v + qf.y * k1v + qf.z * k2v + qf.w * k3v;
                }
            }
            int key = kbase + lane;
            float p[8];
            #pragma unroll
            for (int qi = 0; qi < 8; qi++) {
                float sv = (key <= q0 + qi) ? s[qi] : -1e30f;
                float mx = sv;
                #pragma unroll
                for (int off = 16; off; off >>= 1)
                    mx = fmaxf(mx, __shfl_xor_sync(0xffffffffu, mx, off));
                float mn = fmaxf(m[qi], mx);
                float corr = __expf(m[qi] - mn);
                m[qi] = mn;
                float pv = __expf(sv - mn);
                p[qi] = pv;
                float ps = pv;
                #pragma unroll
                for (int off = 16; off; off >>= 1)
                    ps += __shfl_xor_sync(0xffffffffu, ps, off);
                l[qi] = l[qi] * corr + ps;
                o[qi][0] *= corr; o[qi][1] *= corr; o[qi][2] *= corr; o[qi][3] *= corr;
            }
            #pragma unroll 4
            for (int k = 0; k < 32; k++) {
                float4 vf = *reinterpret_cast<const float4*>(v_s + k * 128 + lane * 4);
                #pragma unroll
                for (int qi = 0; qi < 8; qi++) {
                    float pk = __shfl_sync(0xffffffffu, p[qi], k);
                    o[qi][0] += pk * vf.x; o[qi][1] += pk * vf.y;
                    o[qi][2] += pk * vf.z; o[qi][3] += pk * vf.w;
                }
            }
        }
    }

    #pragma unroll
    for (int qi = 0; qi < 8; qi++) {
        float inv = 1.f / l[qi];
        float vals[4] = { o[qi][0] * inv, o[qi][1] * inv, o[qi][2] * inv, o[qi][3] * inv };
        uint32_t hb[4], lb[4];
        #pragma unroll
        for (int j = 0; j < 4; j++) {
            hb[j] = f2bf_bits(vals[j]);
            lb[j] = f2bf_bits(vals[j] - bf2f(hb[j]));
        }
        size_t base = (size_t)(b * SEQ + q0 + qi) * 2048 + h * 128 + lane * 4;
        *reinterpret_cast<uint2*>(Ohi + base) = make_uint2(hb[0] | (hb[1] << 16), hb[2] | (hb[3] << 16));
        *reinterpret_cast<uint2*>(Olo + base) = make_uint2(lb[0] | (lb[1] << 16), lb[2] | (lb[3] << 16));
    }
}

// ---------------- silu(gate)*up from fused gu, write bf16 hi/lo ----------------
__global__ void silu_mul_split(const float* __restrict__ gu, __nv_bfloat16* __restrict__ hi,
                               __nv_bfloat16* __restrict__ lo) {
    int idx = blockIdx.x * blockDim.x + threadIdx.x;   // over T*1408 (4 elems each)
    if (idx >= T_TOK * 1408) return;
    int row = idx / 1408;
    int c4 = (idx - row * 1408) << 2;
    float4 g = *reinterpret_cast<const float4*>(gu + (size_t)row * 11264 + c4);
    float4 u = *reinterpret_cast<const float4*>(gu + (size_t)row * 11264 + 5632 + c4);
    float vals[4] = {
        (g.x / (1.f + __expf(-g.x))) * u.x,
        (g.y / (1.f + __expf(-g.y))) * u.y,
        (g.z / (1.f + __expf(-g.z))) * u.z,
        (g.w / (1.f + __expf(-g.w))) * u.w };
    uint32_t hb[4], lb[4];
    #pragma unroll
    for (int j = 0; j < 4; j++) {
        hb[j] = f2bf_bits(vals[j]);
        lb[j] = f2bf_bits(vals[j] - bf2f(hb[j]));
    }
    size_t base = (size_t)row * 5632 + c4;
    *reinterpret_cast<uint2*>(hi + base) = make_uint2(hb[0] | (hb[1] << 16), hb[2] | (hb[3] << 16));
    *reinterpret_cast<uint2*>(lo + base) = make_uint2(lb[0] | (lb[1] << 16), lb[2] | (lb[3] << 16));
}

// ---------------- orchestration ----------------
extern "C" void kernel_launch(void* const* d_in, const int* in_sizes, int n_in,
                              void* d_out, int out_size) {
    (void)in_sizes; (void)n_in; (void)out_size;
    const float* x       = (const float*)d_in[0];
    const int*   wq_q    = (const int*)  d_in[1];
    const float* wq_s    = (const float*)d_in[2];
    const float* bq      = (const float*)d_in[3];
    const int*   wk_q    = (const int*)  d_in[4];
    const float* wk_s    = (const float*)d_in[5];
    const float* bk      = (const float*)d_in[6];
    const int*   wv_q    = (const int*)  d_in[7];
    const float* wv_s    = (const float*)d_in[8];
    const float* bv      = (const float*)d_in[9];
    const int*   wo_q    = (const int*)  d_in[10];
    const float* wo_s    = (const float*)d_in[11];
    const int*   gate_q  = (const int*)  d_in[12];
    const float* gate_s  = (const float*)d_in[13];
    const int*   up_q    = (const int*)  d_in[14];
    const float* up_s    = (const float*)d_in[15];
    const int*   down_q  = (const int*)  d_in[16];
    const float* down_s  = (const float*)d_in[17];
    const float* w_in_ln = (const float*)d_in[18];
    const float* w_post_ln = (const float*)d_in[19];
    const int*   offset  = (const int*)  d_in[20];
    float* out = (float*)d_out;

    float *qkv, *x1, *gu, *scales, *biasb;
    __nv_bfloat16 *wbf, *ahi, *alo;
    cudaGetSymbolAddress((void**)&qkv,  g_qkv);
    cudaGetSymbolAddress((void**)&x1,   g_x1);
    cudaGetSymbolAddress((void**)&gu,   g_gu);
    cudaGetSymbolAddress((void**)&wbf,  g_wbf);
    cudaGetSymbolAddress((void**)&ahi,  g_ahi);
    cudaGetSymbolAddress((void**)&alo,  g_alo);
    cudaGetSymbolAddress((void**)&scales, g_scales);
    cudaGetSymbolAddress((void**)&biasb,  g_bias);

    cudaFuncSetAttribute(gemm_mma, cudaFuncAttributeMaxDynamicSharedMemorySize, GSMEM_BYTES);
    cudaFuncSetAttribute(attn_tiled, cudaFuncAttributeMaxDynamicSharedMemorySize, ASMEM_BYTES);

    // 0) weights -> bf16 (layout already fused: qkv rows, gate|up rows)
    {
        struct { const int* q; long off; int n; } ws[7] = {
            {wq_q,   OFF_QKV,  D_MODEL * D_MODEL},
            {wk_q,   OFF_WK,   KV_DIM * D_MODEL},
            {wv_q,   OFF_WV,   KV_DIM * D_MODEL},
            {wo_q,   OFF_WO,   D_MODEL * D_MODEL},
            {gate_q, OFF_GU,   D_FF * D_MODEL},
            {up_q,   OFF_UP,   D_FF * D_MODEL},
            {down_q, OFF_DOWN, D_MODEL * D_FF},
        };
        for (int i = 0; i < 7; i++) {
            int n4 = ws[i].n / 4;
            w2bf_kernel<<<(n4 + 255) / 256, 256>>>(ws[i].q, wbf + ws[i].off, n4);
        }
    }
    // concat scales + biases (device-to-device async copies are graph-safe)
    cudaMemcpyAsync(scales,          wq_s,   65536  * 4, cudaMemcpyDeviceToDevice);
    cudaMemcpyAsync(scales + 65536,  wk_s,   16384  * 4, cudaMemcpyDeviceToDevice);
    cudaMemcpyAsync(scales + 81920,  wv_s,   16384  * 4, cudaMemcpyDeviceToDevice);
    cudaMemcpyAsync(scales + 98304,  gate_s, 180224 * 4, cudaMemcpyDeviceToDevice);
    cudaMemcpyAsync(scales + 278528, up_s,   180224 * 4, cudaMemcpyDeviceToDevice);
    cudaMemcpyAsync(biasb,        bq, 2048 * 4, cudaMemcpyDeviceToDevice);
    cudaMemcpyAsync(biasb + 2048, bk, 512  * 4, cudaMemcpyDeviceToDevice);
    cudaMemcpyAsync(biasb + 2560, bv, 512  * 4, cudaMemcpyDeviceToDevice);

    // 1) input rmsnorm + split
    rmsnorm_split<<<T_TOK, 256>>>(x, w_in_ln, ahi, alo);

    // 2) fused qkv projection
    gemm_mma<<<dim3(3072 / 128, T_TOK / 128), 512, GSMEM_BYTES>>>(
        ahi, alo, wbf + OFF_QKV, scales, biasb, nullptr, qkv, 3072, D_MODEL);

    // 3) RoPE (q heads at col 0, k heads at col 2048)
    rope2_kernel<<<(T_TOK * NHEAD * 64 + 255) / 256, 256>>>(qkv, NHEAD, 0, offset);
    rope2_kernel<<<(T_TOK * NKV * 64 + 255) / 256, 256>>>(qkv, NKV, 2048, offset);

    // 4) attention -> ahi/alo (bf16 split of o)
    attn_tiled<<<dim3(SEQ / 64, NHEAD, 2), 256, ASMEM_BYTES>>>(qkv, ahi, alo);

    // 5) o-projection + residual -> x1
    gemm_mma<<<dim3(D_MODEL / 128, T_TOK / 128), 512, GSMEM_BYTES>>>(
        ahi, alo, wbf + OFF_WO, wo_s, nullptr, x, x1, D_MODEL, D_MODEL);

    // 6) post rmsnorm + split
    rmsnorm_split<<<T_TOK, 256>>>(x1, w_post_ln, ahi, alo);

    // 7) fused gate|up projection
    gemm_mma<<<dim3(11264 / 128, T_TOK / 128), 512, GSMEM_BYTES>>>(
        ahi, alo, wbf + OFF_GU, scales + 98304, nullptr, nullptr, gu, 11264, D_MODEL);

    // 8) silu(gate)*up + split
    silu_mul_split<<<(T_TOK * 1408 + 255) / 256, 256>>>(gu, ahi, alo);

    // 9) down projection + residual -> out
    gemm_mma<<<dim3(D_MODEL / 128, T_TOK / 128), 512, GSMEM_BYTES>>>(
        ahi, alo, wbf + OFF_DOWN, down_s, nullptr, x1, out, D_MODEL, D_FF);
}

// round 5
// speedup vs baseline: 3.6821x; 1.0494x over previous
#include <cuda_runtime.h>
#include <cuda_bf16.h>
#include <cstdint>

#define T_TOK 2048
#define D_MODEL 2048
#define D_FF 5632
#define KV_DIM 512
#define SEQ 1024
#define NHEAD 16
#define NKV 4
#define HDIM 128

// ---------------- scratch (static device globals; no allocation) ----------------
__device__ float g_qkv[T_TOK * 3072];     // fused q|k|v rows
__device__ float g_x1 [T_TOK * D_MODEL];
__device__ float g_gu [T_TOK * 11264];    // fused gate|up
__device__ __nv_bfloat16 g_ahi[T_TOK * D_FF];
__device__ __nv_bfloat16 g_alo[T_TOK * D_FF];

// bf16 weights (int8 values EXACT in bf16; group scales applied in GEMM)
#define W_TOTAL 45088768
#define OFF_QKV  0            // 3072 x 2048  (wq | wk | wv rows)
#define OFF_WO   6291456      // 2048 x 2048
#define OFF_GU   10485760     // 11264 x 2048 (gate | up rows)
#define OFF_DOWN 33554432     // 2048 x 5632
__device__ __nv_bfloat16 g_wbf[W_TOTAL];
__device__ float g_scales[458752];        // qkv scales @0, gu scales @98304
__device__ float g_bias[3072];            // bq|bk|bv

// ---------------- helpers ----------------
__device__ __forceinline__ uint32_t smem_u32(const void* p) {
    uint32_t a;
    asm("{ .reg .u64 t; cvta.to.shared.u64 t, %1; cvt.u32.u64 %0, t; }" : "=r"(a) : "l"(p));
    return a;
}
__device__ __forceinline__ uint32_t sw128(uint32_t off) { return off ^ ((off >> 3) & 0x70u); }
__device__ __forceinline__ uint32_t f2bf_bits(float f) {
    uint32_t u = __float_as_uint(f);
    return (u + 0x7fffu + ((u >> 16) & 1u)) >> 16;
}
__device__ __forceinline__ float bf2f(uint32_t b) { return __uint_as_float(b << 16); }

#define CP16(saddr, gptr) \
    asm volatile("cp.async.cg.shared.global [%0], [%1], 16;" :: "r"(saddr), "l"(gptr))
#define CP4(saddr, gptr) \
    asm volatile("cp.async.ca.shared.global [%0], [%1], 4;" :: "r"(saddr), "l"(gptr))
#define CP_COMMIT() asm volatile("cp.async.commit_group;" ::: "memory")
#define CP_WAIT(n)  asm volatile("cp.async.wait_group %0;" :: "n"(n) : "memory")

#define LDSM_X4(r, addr) \
    asm volatile("ldmatrix.sync.aligned.m8n8.x4.shared.b16 {%0,%1,%2,%3}, [%4];" \
        : "=r"((r)[0]), "=r"((r)[1]), "=r"((r)[2]), "=r"((r)[3]) : "r"(addr))

__device__ __forceinline__ void mma_bf16(float* c, const uint32_t* a, uint32_t b0, uint32_t b1) {
    asm volatile("mma.sync.aligned.m16n8k16.row.col.f32.bf16.bf16.f32 "
        "{%0,%1,%2,%3}, {%4,%5,%6,%7}, {%8,%9}, {%0,%1,%2,%3};"
        : "+f"(c[0]), "+f"(c[1]), "+f"(c[2]), "+f"(c[3])
        : "r"(a[0]), "r"(a[1]), "r"(a[2]), "r"(a[3]), "r"(b0), "r"(b1));
}

// ---------------- fused weight convert (all 7 weights, one launch) ----------------
// g_wbf layout order: qkv(q|k|v) | wo | gate | up | down (contiguous)
__global__ void w2bf_all(const int* __restrict__ wq, const int* __restrict__ wk,
                         const int* __restrict__ wv, const int* __restrict__ wo,
                         const int* __restrict__ wg, const int* __restrict__ wu,
                         const int* __restrict__ wd, __nv_bfloat16* __restrict__ w) {
    int idx = blockIdx.x * blockDim.x + threadIdx.x;   // 4-vector index
    if (idx >= W_TOTAL / 4) return;
    const int* src;
    // cumulative 4-vec boundaries
    if      (idx < 1048576) src = wq + idx * 4;
    else if (idx < 1310720) src = wk + (idx - 1048576) * 4;
    else if (idx < 1572864) src = wv + (idx - 1310720) * 4;
    else if (idx < 2621440) src = wo + (idx - 1572864) * 4;
    else if (idx < 5505024) src = wg + (idx - 2621440) * 4;
    else if (idx < 8388608) src = wu + (idx - 5505024) * 4;
    else                    src = wd + (idx - 8388608) * 4;
    int4 v = *reinterpret_cast<const int4*>(src);
    uint32_t b0 = f2bf_bits((float)v.x), b1 = f2bf_bits((float)v.y);
    uint32_t b2 = f2bf_bits((float)v.z), b3 = f2bf_bits((float)v.w);
    *reinterpret_cast<uint2*>(w + (size_t)idx * 4) = make_uint2(b0 | (b1 << 16), b2 | (b3 << 16));
}

// ---------------- RMSNorm fused with hi/lo split ----------------
__global__ void rmsnorm_split(const float* __restrict__ x, const float* __restrict__ w,
                              __nv_bfloat16* __restrict__ hi, __nv_bfloat16* __restrict__ lo) {
    int row = blockIdx.x, tid = threadIdx.x;
    const float4* xr = reinterpret_cast<const float4*>(x + (size_t)row * D_MODEL);
    const float4* wr = reinterpret_cast<const float4*>(w);

    float4 v0 = xr[tid], v1 = xr[tid + 256];
    float s = v0.x*v0.x + v0.y*v0.y + v0.z*v0.z + v0.w*v0.w
            + v1.x*v1.x + v1.y*v1.y + v1.z*v1.z + v1.w*v1.w;
    #pragma unroll
    for (int off = 16; off; off >>= 1) s += __shfl_xor_sync(0xffffffffu, s, off);
    __shared__ float red[8];
    if ((tid & 31) == 0) red[tid >> 5] = s;
    __syncthreads();
    float tot = 0.f;
    #pragma unroll
    for (int i = 0; i < 8; i++) tot += red[i];
    float inv = rsqrtf(tot * (1.0f / D_MODEL) + 1e-6f);

    float4 w0 = wr[tid], w1 = wr[tid + 256];
    float vals[8] = { v0.x*inv*w0.x, v0.y*inv*w0.y, v0.z*inv*w0.z, v0.w*inv*w0.w,
                      v1.x*inv*w1.x, v1.y*inv*w1.y, v1.z*inv*w1.z, v1.w*inv*w1.w };
    uint32_t hb[8], lb[8];
    #pragma unroll
    for (int i = 0; i < 8; i++) {
        hb[i] = f2bf_bits(vals[i]);
        lb[i] = f2bf_bits(vals[i] - bf2f(hb[i]));
    }
    uint2* hp = reinterpret_cast<uint2*>(hi + (size_t)row * D_MODEL);
    uint2* lp = reinterpret_cast<uint2*>(lo + (size_t)row * D_MODEL);
    hp[tid]       = make_uint2(hb[0] | (hb[1] << 16), hb[2] | (hb[3] << 16));
    hp[tid + 256] = make_uint2(hb[4] | (hb[5] << 16), hb[6] | (hb[7] << 16));
    lp[tid]       = make_uint2(lb[0] | (lb[1] << 16), lb[2] | (lb[3] << 16));
    lp[tid + 256] = make_uint2(lb[4] | (lb[5] << 16), lb[6] | (lb[7] << 16));
}

// ---------------- tensor-core GEMM via mma.sync, 3-stage cp.async ring ----------------
#define STAGE_BYTES 49664
#define S_AHI 0
#define S_ALO 16384
#define S_W   32768
#define S_SC  49152
#define GSMEM_BYTES (3 * STAGE_BYTES + 1024)

__global__ void __launch_bounds__(512, 1)
gemm_mma(const __nv_bfloat16* __restrict__ Ahi, const __nv_bfloat16* __restrict__ Alo,
         const __nv_bfloat16* __restrict__ W, const float* __restrict__ Ws,
         const float* __restrict__ bias, const float* __restrict__ res,
         float* __restrict__ C, int O, int K) {
    extern __shared__ char dsm[];
    uint32_t sbraw = smem_u32(dsm);
    uint32_t sb = (sbraw + 1023u) & ~1023u;
    char* bp = dsm + (sb - sbraw);

    int tid = threadIdx.x, lane = tid & 31, wid = tid >> 5;
    int wm = wid >> 2, wn = wid & 3;
    int mb = blockIdx.y * 128, nb = blockIdx.x * 128;
    int nc = K >> 6;

    // loader lambda (manually inlined): stage s, k-tile index c
    int lrow0 = tid >> 3, lkc = (tid & 7) << 3;

    float acc[2][4][4];
    #pragma unroll
    for (int a = 0; a < 2; a++)
        #pragma unroll
        for (int b = 0; b < 4; b++)
            #pragma unroll
            for (int d = 0; d < 4; d++) acc[a][b][d] = 0.f;

    // prologue: stages 0 and 1
    #pragma unroll
    for (int pc = 0; pc < 2; pc++) {
        uint32_t ss = sb + (uint32_t)pc * STAGE_BYTES;
        int k0 = pc << 6;
        #pragma unroll
        for (int it = 0; it < 2; it++) {
            int row = lrow0 + it * 64;
            uint32_t so = sw128((uint32_t)(row * 128 + lkc * 2));
            CP16(ss + S_AHI + so, Ahi + (size_t)(mb + row) * K + k0 + lkc);
            CP16(ss + S_ALO + so, Alo + (size_t)(mb + row) * K + k0 + lkc);
            CP16(ss + S_W + so,   W   + (size_t)(nb + row) * K + k0 + lkc);
        }
        if (tid < 128) CP4(ss + S_SC + tid * 4, Ws + (size_t)(nb + tid) * nc + pc);
        CP_COMMIT();
    }

    int stage = 0;
    for (int c = 0; c < nc; c++) {
        if (c + 1 < nc) { CP_WAIT(1); } else { CP_WAIT(0); }
        __syncthreads();                       // retires reads of stage (c+2)%3 from iter c-1

        // issue loads for k-tile c+2 into stage (c+2)%3
        if (c + 2 < nc) {
            int snum = stage + 2; if (snum >= 3) snum -= 3;
            uint32_t ss = sb + (uint32_t)snum * STAGE_BYTES;
            int k0 = (c + 2) << 6;
            #pragma unroll
            for (int it = 0; it < 2; it++) {
                int row = lrow0 + it * 64;
                uint32_t so = sw128((uint32_t)(row * 128 + lkc * 2));
                CP16(ss + S_AHI + so, Ahi + (size_t)(mb + row) * K + k0 + lkc);
                CP16(ss + S_ALO + so, Alo + (size_t)(mb + row) * K + k0 + lkc);
                CP16(ss + S_W + so,   W   + (size_t)(nb + row) * K + k0 + lkc);
            }
            if (tid < 128) CP4(ss + S_SC + tid * 4, Ws + (size_t)(nb + tid) * nc + (c + 2));
            CP_COMMIT();
        }

        uint32_t scur = sb + (uint32_t)stage * STAGE_BYTES;
        float gacc[2][4][4];
        #pragma unroll
        for (int a = 0; a < 2; a++)
            #pragma unroll
            for (int b = 0; b < 4; b++)
                #pragma unroll
                for (int d = 0; d < 4; d++) gacc[a][b][d] = 0.f;

        #pragma unroll
        for (int ks = 0; ks < 4; ks++) {
            int kh = ks << 4;
            uint32_t ah[2][4], al[2][4], bfr[2][4];
            #pragma unroll
            for (int mf = 0; mf < 2; mf++) {
                int row = wm * 32 + mf * 16 + (lane & 7) + ((lane >> 3) & 1) * 8;
                int kk = kh + ((lane >> 4) << 3);
                uint32_t so = sw128((uint32_t)(row * 128 + kk * 2));
                LDSM_X4(ah[mf], scur + S_AHI + so);
                LDSM_X4(al[mf], scur + S_ALO + so);
            }
            #pragma unroll
            for (int np = 0; np < 2; np++) {
                int n = wn * 32 + np * 16 + (lane & 7) + ((lane >> 4) << 3);
                int kk = kh + ((lane >> 3) & 1) * 8;
                LDSM_X4(bfr[np], scur + S_W + sw128((uint32_t)(n * 128 + kk * 2)));
            }
            #pragma unroll
            for (int mf = 0; mf < 2; mf++)
                #pragma unroll
                for (int nf = 0; nf < 4; nf++) {
                    uint32_t b0 = bfr[nf >> 1][(nf & 1) * 2], b1 = bfr[nf >> 1][(nf & 1) * 2 + 1];
                    mma_bf16(gacc[mf][nf], ah[mf], b0, b1);
                    mma_bf16(gacc[mf][nf], al[mf], b0, b1);
                }
        }

        const float* sp = reinterpret_cast<const float*>(bp + stage * STAGE_BYTES + S_SC);
        #pragma unroll
        for (int nf = 0; nf < 4; nf++) {
            int cc = wn * 32 + nf * 8 + (lane & 3) * 2;
            float s0 = sp[cc], s1 = sp[cc + 1];
            #pragma unroll
            for (int mf = 0; mf < 2; mf++) {
                acc[mf][nf][0] += gacc[mf][nf][0] * s0;
                acc[mf][nf][1] += gacc[mf][nf][1] * s1;
                acc[mf][nf][2] += gacc[mf][nf][2] * s0;
                acc[mf][nf][3] += gacc[mf][nf][3] * s1;
            }
        }
        if (++stage == 3) stage = 0;
    }

    #pragma unroll
    for (int mf = 0; mf < 2; mf++) {
        int row = mb + wm * 32 + mf * 16 + (lane >> 2);
        #pragma unroll
        for (int nf = 0; nf < 4; nf++) {
            int col = nb + wn * 32 + nf * 8 + (lane & 3) * 2;
            float v0 = acc[mf][nf][0], v1 = acc[mf][nf][1];
            float v2 = acc[mf][nf][2], v3 = acc[mf][nf][3];
            if (bias) {
                float b0 = bias[col], b1 = bias[col + 1];
                v0 += b0; v1 += b1; v2 += b0; v3 += b1;
            }
            size_t o0 = (size_t)row * O + col;
            size_t o1 = (size_t)(row + 8) * O + col;
            if (res) {
                float2 r0 = *reinterpret_cast<const float2*>(res + o0);
                float2 r1 = *reinterpret_cast<const float2*>(res + o1);
                v0 += r0.x; v1 += r0.y; v2 += r1.x; v3 += r1.y;
            }
            *reinterpret_cast<float2*>(C + o0) = make_float2(v0, v1);
            *reinterpret_cast<float2*>(C + o1) = make_float2(v2, v3);
        }
    }
}

// ---------------- fused RoPE on q (16 heads) + k (4 heads) ----------------
__global__ void rope_all(float* __restrict__ X, const int* __restrict__ offp) {
    int idx = blockIdx.x * blockDim.x + threadIdx.x;
    int total = T_TOK * 20 * 64;
    if (idx >= total) return;
    int j = idx & 63;
    int rest = idx >> 6;
    int h = rest % 20;
    int t = rest / 20;
    int s = t & (SEQ - 1);
    int col = (h < 16) ? h * 128 : 2048 + (h - 16) * 128;
    float pos = (float)(s + *offp);
    float inv = exp2f(-(float)j * (2.0f / 128.0f) * 19.931568569324174f);
    float ang = pos * inv;
    float c, sn;
    sincosf(ang, &sn, &c);
    float* p = X + (size_t)t * 3072 + col + j;
    float x1 = p[0], x2 = p[64];
    p[0]  = x1 * c - x2 * sn;
    p[64] = x2 * c + x1 * sn;
}

// ---------------- smem-tiled flash attention (fp32), writes bf16 hi/lo ----------------
#define ASMEM_BYTES 65536

__global__ void __launch_bounds__(256)
attn_tiled(const float* __restrict__ qkv, __nv_bfloat16* __restrict__ Ohi,
           __nv_bfloat16* __restrict__ Olo) {
    extern __shared__ float asmf[];
    float* q_s = asmf;               // [64][128]
    float* kT  = asmf + 64 * 128;    // [128][32]
    float* v_s = kT + 128 * 32;      // [32][128]

    int tid = threadIdx.x, warp = tid >> 5, lane = tid & 31;
    int Qb = ((int)gridDim.x - 1 - (int)blockIdx.x) * 64;
    int h = blockIdx.y, b = blockIdx.z, kh = h >> 2;
    const float scale = 0.08838834764831843f;

    for (int i = tid; i < 64 * 32; i += 256) {
        int row = i >> 5, c4 = (i & 31) << 2;
        float4 qf = *reinterpret_cast<const float4*>(
            qkv + (size_t)(b * SEQ + Qb + row) * 3072 + h * 128 + c4);
        qf.x *= scale; qf.y *= scale; qf.z *= scale; qf.w *= scale;
        *reinterpret_cast<float4*>(q_s + row * 128 + c4) = qf;
    }

    float m[8], l[8], o[8][4];
    #pragma unroll
    for (int i = 0; i < 8; i++) {
        m[i] = -1e30f; l[i] = 0.f;
        o[i][0] = o[i][1] = o[i][2] = o[i][3] = 0.f;
    }
    int q0 = Qb + warp * 8;
    int nt = (Qb >> 5) + 2;

    for (int t = 0; t < nt; t++) {
        int kbase = t << 5;
        __syncthreads();
        {
            int key = tid & 31, dch = tid >> 5;
            const float* kg = qkv + (size_t)(b * SEQ + kbase + key) * 3072 + 2048 + kh * 128 + dch * 16;
            const float* vg = kg + 512;
            #pragma unroll
            for (int j = 0; j < 4; j++) {
                float4 kf = *reinterpret_cast<const float4*>(kg + j * 4);
                int d0 = dch * 16 + j * 4;
                kT[(d0 + 0) * 32 + key] = kf.x;
                kT[(d0 + 1) * 32 + key] = kf.y;
                kT[(d0 + 2) * 32 + key] = kf.z;
                kT[(d0 + 3) * 32 + key] = kf.w;
                *reinterpret_cast<float4*>(v_s + key * 128 + d0) =
                    *reinterpret_cast<const float4*>(vg + j * 4);
            }
        }
        __syncthreads();

        if (kbase <= q0 + 7) {
            float s[8];
            #pragma unroll
            for (int i = 0; i < 8; i++) s[i] = 0.f;
            #pragma unroll 4
            for (int d = 0; d < 128; d += 4) {
                float k0v = kT[d * 32 + lane],       k1v = kT[(d + 1) * 32 + lane];
                float k2v = kT[(d + 2) * 32 + lane], k3v = kT[(d + 3) * 32 + lane];
                const float* qrow = q_s + warp * 8 * 128 + d;
                #pragma unroll
                for (int qi = 0; qi < 8; qi++) {
                    float4 qf = *reinterpret_cast<const float4*>(qrow + qi * 128);
                    s[qi] += qf.x * k0v + qf.y * k1v + qf.z * k2v + qf.w * k3v;
                }
            }
            int key = kbase + lane;
            float p[8];
            #pragma unroll
            for (int qi = 0; qi < 8; qi++) {
                float sv = (key <= q0 + qi) ? s[qi] : -1e30f;
                float mx = sv;
                #pragma unroll
                for (int off = 16; off; off >>= 1)
                    mx = fmaxf(mx, __shfl_xor_sync(0xffffffffu, mx, off));
                float mn = fmaxf(m[qi], mx);
                float corr = __expf(m[qi] - mn);
                m[qi] = mn;
                float pv = __expf(sv - mn);
                p[qi] = pv;
                float ps = pv;
                #pragma unroll
                for (int off = 16; off; off >>= 1)
                    ps += __shfl_xor_sync(0xffffffffu, ps, off);
                l[qi] = l[qi] * corr + ps;
                o[qi][0] *= corr; o[qi][1] *= corr; o[qi][2] *= corr; o[qi][3] *= corr;
            }
            #pragma unroll 4
            for (int k = 0; k < 32; k++) {
                float4 vf = *reinterpret_cast<const float4*>(v_s + k * 128 + lane * 4);
                #pragma unroll
                for (int qi = 0; qi < 8; qi++) {
                    float pk = __shfl_sync(0xffffffffu, p[qi], k);
                    o[qi][0] += pk * vf.x; o[qi][1] += pk * vf.y;
                    o[qi][2] += pk * vf.z; o[qi][3] += pk * vf.w;
                }
            }
        }
    }

    #pragma unroll
    for (int qi = 0; qi < 8; qi++) {
        float inv = 1.f / l[qi];
        float vals[4] = { o[qi][0] * inv, o[qi][1] * inv, o[qi][2] * inv, o[qi][3] * inv };
        uint32_t hb[4], lb[4];
        #pragma unroll
        for (int j = 0; j < 4; j++) {
            hb[j] = f2bf_bits(vals[j]);
            lb[j] = f2bf_bits(vals[j] - bf2f(hb[j]));
        }
        size_t base = (size_t)(b * SEQ + q0 + qi) * 2048 + h * 128 + lane * 4;
        *reinterpret_cast<uint2*>(Ohi + base) = make_uint2(hb[0] | (hb[1] << 16), hb[2] | (hb[3] << 16));
        *reinterpret_cast<uint2*>(Olo + base) = make_uint2(lb[0] | (lb[1] << 16), lb[2] | (lb[3] << 16));
    }
}

// ---------------- silu(gate)*up from fused gu, write bf16 hi/lo ----------------
__global__ void silu_mul_split(const float* __restrict__ gu, __nv_bfloat16* __restrict__ hi,
                               __nv_bfloat16* __restrict__ lo) {
    int idx = blockIdx.x * blockDim.x + threadIdx.x;
    if (idx >= T_TOK * 1408) return;
    int row = idx / 1408;
    int c4 = (idx - row * 1408) << 2;
    float4 g = *reinterpret_cast<const float4*>(gu + (size_t)row * 11264 + c4);
    float4 u = *reinterpret_cast<const float4*>(gu + (size_t)row * 11264 + 5632 + c4);
    float vals[4] = {
        (g.x / (1.f + __expf(-g.x))) * u.x,
        (g.y / (1.f + __expf(-g.y))) * u.y,
        (g.z / (1.f + __expf(-g.z))) * u.z,
        (g.w / (1.f + __expf(-g.w))) * u.w };
    uint32_t hb[4], lb[4];
    #pragma unroll
    for (int j = 0; j < 4; j++) {
        hb[j] = f2bf_bits(vals[j]);
        lb[j] = f2bf_bits(vals[j] - bf2f(hb[j]));
    }
    size_t base = (size_t)row * 5632 + c4;
    *reinterpret_cast<uint2*>(hi + base) = make_uint2(hb[0] | (hb[1] << 16), hb[2] | (hb[3] << 16));
    *reinterpret_cast<uint2*>(lo + base) = make_uint2(lb[0] | (lb[1] << 16), lb[2] | (lb[3] << 16));
}

// ---------------- orchestration ----------------
extern "C" void kernel_launch(void* const* d_in, const int* in_sizes, int n_in,
                              void* d_out, int out_size) {
    (void)in_sizes; (void)n_in; (void)out_size;
    const float* x       = (const float*)d_in[0];
    const int*   wq_q    = (const int*)  d_in[1];
    const float* wq_s    = (const float*)d_in[2];
    const float* bq      = (const float*)d_in[3];
    const int*   wk_q    = (const int*)  d_in[4];
    const float* wk_s    = (const float*)d_in[5];
    const float* bk      = (const float*)d_in[6];
    const int*   wv_q    = (const int*)  d_in[7];
    const float* wv_s    = (const float*)d_in[8];
    const float* bv      = (const float*)d_in[9];
    const int*   wo_q    = (const int*)  d_in[10];
    const float* wo_s    = (const float*)d_in[11];
    const int*   gate_q  = (const int*)  d_in[12];
    const float* gate_s  = (const float*)d_in[13];
    const int*   up_q    = (const int*)  d_in[14];
    const float* up_s    = (const float*)d_in[15];
    const int*   down_q  = (const int*)  d_in[16];
    const float* down_s  = (const float*)d_in[17];
    const float* w_in_ln = (const float*)d_in[18];
    const float* w_post_ln = (const float*)d_in[19];
    const int*   offset  = (const int*)  d_in[20];
    float* out = (float*)d_out;

    float *qkv, *x1, *gu, *scales, *biasb;
    __nv_bfloat16 *wbf, *ahi, *alo;
    cudaGetSymbolAddress((void**)&qkv,  g_qkv);
    cudaGetSymbolAddress((void**)&x1,   g_x1);
    cudaGetSymbolAddress((void**)&gu,   g_gu);
    cudaGetSymbolAddress((void**)&wbf,  g_wbf);
    cudaGetSymbolAddress((void**)&ahi,  g_ahi);
    cudaGetSymbolAddress((void**)&alo,  g_alo);
    cudaGetSymbolAddress((void**)&scales, g_scales);
    cudaGetSymbolAddress((void**)&biasb,  g_bias);

    cudaFuncSetAttribute(gemm_mma, cudaFuncAttributeMaxDynamicSharedMemorySize, GSMEM_BYTES);
    cudaFuncSetAttribute(attn_tiled, cudaFuncAttributeMaxDynamicSharedMemorySize, ASMEM_BYTES);

    // scale/bias concat (D2D async copies, graph-safe)
    cudaMemcpyAsync(scales,          wq_s,   65536  * 4, cudaMemcpyDeviceToDevice);
    cudaMemcpyAsync(scales + 65536,  wk_s,   16384  * 4, cudaMemcpyDeviceToDevice);
    cudaMemcpyAsync(scales + 81920,  wv_s,   16384  * 4, cudaMemcpyDeviceToDevice);
    cudaMemcpyAsync(scales + 98304,  gate_s, 180224 * 4, cudaMemcpyDeviceToDevice);
    cudaMemcpyAsync(scales + 278528, up_s,   180224 * 4, cudaMemcpyDeviceToDevice);
    cudaMemcpyAsync(biasb,        bq, 2048 * 4, cudaMemcpyDeviceToDevice);
    cudaMemcpyAsync(biasb + 2048, bk, 512  * 4, cudaMemcpyDeviceToDevice);
    cudaMemcpyAsync(biasb + 2560, bv, 512  * 4, cudaMemcpyDeviceToDevice);

    // launch #1: all weights -> bf16
    w2bf_all<<<(W_TOTAL / 4 + 255) / 256, 256>>>(wq_q, wk_q, wv_q, wo_q, gate_q, up_q, down_q, wbf);

    // #2: input rmsnorm + split
    rmsnorm_split<<<T_TOK, 256>>>(x, w_in_ln, ahi, alo);

    // #3: fused qkv projection
    gemm_mma<<<dim3(3072 / 128, T_TOK / 128), 512, GSMEM_BYTES>>>(
        ahi, alo, wbf + OFF_QKV, scales, biasb, nullptr, qkv, 3072, D_MODEL);

    // #4: fused RoPE (q + k heads)
    rope_all<<<(T_TOK * 20 * 64 + 255) / 256, 256>>>(qkv, offset);

    // #5: attention -> ahi/alo
    attn_tiled<<<dim3(SEQ / 64, NHEAD, 2), 256, ASMEM_BYTES>>>(qkv, ahi, alo);

    // #6: o-projection + residual -> x1   (this one lands under ncu -s 5 -c 1)
    gemm_mma<<<dim3(D_MODEL / 128, T_TOK / 128), 512, GSMEM_BYTES>>>(
        ahi, alo, wbf + OFF_WO, wo_s, nullptr, x, x1, D_MODEL, D_MODEL);

    // #7: post rmsnorm + split
    rmsnorm_split<<<T_TOK, 256>>>(x1, w_post_ln, ahi, alo);

    // #8: fused gate|up projection
    gemm_mma<<<dim3(11264 / 128, T_TOK / 128), 512, GSMEM_BYTES>>>(
        ahi, alo, wbf + OFF_GU, scales + 98304, nullptr, nullptr, gu, 11264, D_MODEL);

    // #9: silu(gate)*up + split
    silu_mul_split<<<(T_TOK * 1408 + 255) / 256, 256>>>(gu, ahi, alo);

    // #10: down projection + residual -> out
    gemm_mma<<<dim3(D_MODEL / 128, T_TOK / 128), 512, GSMEM_BYTES>>>(
        ahi, alo, wbf + OFF_DOWN, down_s, nullptr, x1, out, D_MODEL, D_FF);
}

// round 6
// speedup vs baseline: 3.7297x; 1.0129x over previous
#include <cuda_runtime.h>
#include <cuda_bf16.h>
#include <cstdint>

#define T_TOK 2048
#define D_MODEL 2048
#define D_FF 5632
#define KV_DIM 512
#define SEQ 1024
#define NHEAD 16
#define NKV 4
#define HDIM 128

// ---------------- scratch (static device globals; no allocation) ----------------
__device__ float g_qkv[T_TOK * 3072];     // fused q|k|v rows
__device__ float g_x1 [T_TOK * D_MODEL];
__device__ float g_gu [T_TOK * 11264];    // fused gate|up
__device__ __nv_bfloat16 g_ahi[T_TOK * D_FF];
__device__ __nv_bfloat16 g_alo[T_TOK * D_FF];

// bf16 weights (int8 values EXACT in bf16; group scales applied in GEMM)
#define W_TOTAL 45088768
#define OFF_QKV  0            // 3072 x 2048  (wq | wk | wv rows)
#define OFF_WO   6291456      // 2048 x 2048
#define OFF_GU   10485760     // 11264 x 2048 (gate | up rows)
#define OFF_DOWN 33554432     // 2048 x 5632
__device__ __nv_bfloat16 g_wbf[W_TOTAL];
__device__ float g_scales[458752];        // qkv scales @0, gu scales @98304
__device__ float g_bias[3072];            // bq|bk|bv

// ---------------- helpers ----------------
__device__ __forceinline__ uint32_t smem_u32(const void* p) {
    uint32_t a;
    asm("{ .reg .u64 t; cvta.to.shared.u64 t, %1; cvt.u32.u64 %0, t; }" : "=r"(a) : "l"(p));
    return a;
}
__device__ __forceinline__ uint32_t sw128(uint32_t off) { return off ^ ((off >> 3) & 0x70u); }
__device__ __forceinline__ uint32_t f2bf_bits(float f) {
    uint32_t u = __float_as_uint(f);
    return (u + 0x7fffu + ((u >> 16) & 1u)) >> 16;
}
__device__ __forceinline__ float bf2f(uint32_t b) { return __uint_as_float(b << 16); }

#define CP16(saddr, gptr) \
    asm volatile("cp.async.cg.shared.global [%0], [%1], 16;" :: "r"(saddr), "l"(gptr))
#define CP4(saddr, gptr) \
    asm volatile("cp.async.ca.shared.global [%0], [%1], 4;" :: "r"(saddr), "l"(gptr))
#define CP_COMMIT() asm volatile("cp.async.commit_group;" ::: "memory")
#define CP_WAIT(n)  asm volatile("cp.async.wait_group %0;" :: "n"(n) : "memory")

#define LDSM_X4(r, addr) \
    asm volatile("ldmatrix.sync.aligned.m8n8.x4.shared.b16 {%0,%1,%2,%3}, [%4];" \
        : "=r"((r)[0]), "=r"((r)[1]), "=r"((r)[2]), "=r"((r)[3]) : "r"(addr))

__device__ __forceinline__ void mma_bf16(float* c, const uint32_t* a, uint32_t b0, uint32_t b1) {
    asm volatile("mma.sync.aligned.m16n8k16.row.col.f32.bf16.bf16.f32 "
        "{%0,%1,%2,%3}, {%4,%5,%6,%7}, {%8,%9}, {%0,%1,%2,%3};"
        : "+f"(c[0]), "+f"(c[1]), "+f"(c[2]), "+f"(c[3])
        : "r"(a[0]), "r"(a[1]), "r"(a[2]), "r"(a[3]), "r"(b0), "r"(b1));
}

// ---------------- fused weight convert (all 7 weights, one launch) ----------------
__global__ void w2bf_all(const int* __restrict__ wq, const int* __restrict__ wk,
                         const int* __restrict__ wv, const int* __restrict__ wo,
                         const int* __restrict__ wg, const int* __restrict__ wu,
                         const int* __restrict__ wd, __nv_bfloat16* __restrict__ w) {
    int idx = blockIdx.x * blockDim.x + threadIdx.x;   // 4-vector index
    if (idx >= W_TOTAL / 4) return;
    const int* src;
    if      (idx < 1048576) src = wq + idx * 4;
    else if (idx < 1310720) src = wk + (idx - 1048576) * 4;
    else if (idx < 1572864) src = wv + (idx - 1310720) * 4;
    else if (idx < 2621440) src = wo + (idx - 1572864) * 4;
    else if (idx < 5505024) src = wg + (idx - 2621440) * 4;
    else if (idx < 8388608) src = wu + (idx - 5505024) * 4;
    else                    src = wd + (idx - 8388608) * 4;
    int4 v = *reinterpret_cast<const int4*>(src);
    uint32_t b0 = f2bf_bits((float)v.x), b1 = f2bf_bits((float)v.y);
    uint32_t b2 = f2bf_bits((float)v.z), b3 = f2bf_bits((float)v.w);
    *reinterpret_cast<uint2*>(w + (size_t)idx * 4) = make_uint2(b0 | (b1 << 16), b2 | (b3 << 16));
}

// ---------------- RMSNorm fused with hi/lo split ----------------
__global__ void rmsnorm_split(const float* __restrict__ x, const float* __restrict__ w,
                              __nv_bfloat16* __restrict__ hi, __nv_bfloat16* __restrict__ lo) {
    int row = blockIdx.x, tid = threadIdx.x;
    const float4* xr = reinterpret_cast<const float4*>(x + (size_t)row * D_MODEL);
    const float4* wr = reinterpret_cast<const float4*>(w);

    float4 v0 = xr[tid], v1 = xr[tid + 256];
    float s = v0.x*v0.x + v0.y*v0.y + v0.z*v0.z + v0.w*v0.w
            + v1.x*v1.x + v1.y*v1.y + v1.z*v1.z + v1.w*v1.w;
    #pragma unroll
    for (int off = 16; off; off >>= 1) s += __shfl_xor_sync(0xffffffffu, s, off);
    __shared__ float red[8];
    if ((tid & 31) == 0) red[tid >> 5] = s;
    __syncthreads();
    float tot = 0.f;
    #pragma unroll
    for (int i = 0; i < 8; i++) tot += red[i];
    float inv = rsqrtf(tot * (1.0f / D_MODEL) + 1e-6f);

    float4 w0 = wr[tid], w1 = wr[tid + 256];
    float vals[8] = { v0.x*inv*w0.x, v0.y*inv*w0.y, v0.z*inv*w0.z, v0.w*inv*w0.w,
                      v1.x*inv*w1.x, v1.y*inv*w1.y, v1.z*inv*w1.z, v1.w*inv*w1.w };
    uint32_t hb[8], lb[8];
    #pragma unroll
    for (int i = 0; i < 8; i++) {
        hb[i] = f2bf_bits(vals[i]);
        lb[i] = f2bf_bits(vals[i] - bf2f(hb[i]));
    }
    uint2* hp = reinterpret_cast<uint2*>(hi + (size_t)row * D_MODEL);
    uint2* lp = reinterpret_cast<uint2*>(lo + (size_t)row * D_MODEL);
    hp[tid]       = make_uint2(hb[0] | (hb[1] << 16), hb[2] | (hb[3] << 16));
    hp[tid + 256] = make_uint2(hb[4] | (hb[5] << 16), hb[6] | (hb[7] << 16));
    lp[tid]       = make_uint2(lb[0] | (lb[1] << 16), lb[2] | (lb[3] << 16));
    lp[tid + 256] = make_uint2(lb[4] | (lb[5] << 16), lb[6] | (lb[7] << 16));
}

// ---------------- tensor-core GEMM via mma.sync, 4-stage cp.async ring ----------------
#define NSTAGE 4
#define STAGE_BYTES 49664
#define S_AHI 0
#define S_ALO 16384
#define S_W   32768
#define S_SC  49152
#define GSMEM_BYTES (NSTAGE * STAGE_BYTES + 1024)

__global__ void __launch_bounds__(512, 1)
gemm_mma(const __nv_bfloat16* __restrict__ Ahi, const __nv_bfloat16* __restrict__ Alo,
         const __nv_bfloat16* __restrict__ W, const float* __restrict__ Ws,
         const float* __restrict__ bias, const float* __restrict__ res,
         float* __restrict__ C, int O, int K) {
    extern __shared__ char dsm[];
    uint32_t sbraw = smem_u32(dsm);
    uint32_t sb = (sbraw + 1023u) & ~1023u;
    char* bp = dsm + (sb - sbraw);

    int tid = threadIdx.x, lane = tid & 31, wid = tid >> 5;
    int wm = wid >> 2, wn = wid & 3;
    int mb = blockIdx.y * 128, nb = blockIdx.x * 128;
    int nc = K >> 6;

    int lrow0 = tid >> 3, lkc = (tid & 7) << 3;

    float acc[2][4][4];
    #pragma unroll
    for (int a = 0; a < 2; a++)
        #pragma unroll
        for (int b = 0; b < 4; b++)
            #pragma unroll
            for (int d = 0; d < 4; d++) acc[a][b][d] = 0.f;

    // prologue: stages 0..2
    #pragma unroll
    for (int pc = 0; pc < NSTAGE - 1; pc++) {
        uint32_t ss = sb + (uint32_t)pc * STAGE_BYTES;
        int k0 = pc << 6;
        #pragma unroll
        for (int it = 0; it < 2; it++) {
            int row = lrow0 + it * 64;
            uint32_t so = sw128((uint32_t)(row * 128 + lkc * 2));
            CP16(ss + S_AHI + so, Ahi + (size_t)(mb + row) * K + k0 + lkc);
            CP16(ss + S_ALO + so, Alo + (size_t)(mb + row) * K + k0 + lkc);
            CP16(ss + S_W + so,   W   + (size_t)(nb + row) * K + k0 + lkc);
        }
        if (tid < 128) CP4(ss + S_SC + tid * 4, Ws + (size_t)(nb + tid) * nc + pc);
        CP_COMMIT();
    }

    int stage = 0;
    for (int c = 0; c < nc; c++) {
        int rem = nc - 1 - c;
        if (rem >= 2) { CP_WAIT(2); }
        else if (rem == 1) { CP_WAIT(1); }
        else { CP_WAIT(0); }
        __syncthreads();                       // retires reads of stage (c+3)%4 from iter c-1

        // issue loads for k-tile c+3 into stage (c+3)%4
        if (c + NSTAGE - 1 < nc) {
            int snum = stage + NSTAGE - 1; if (snum >= NSTAGE) snum -= NSTAGE;
            uint32_t ss = sb + (uint32_t)snum * STAGE_BYTES;
            int k0 = (c + NSTAGE - 1) << 6;
            #pragma unroll
            for (int it = 0; it < 2; it++) {
                int row = lrow0 + it * 64;
                uint32_t so = sw128((uint32_t)(row * 128 + lkc * 2));
                CP16(ss + S_AHI + so, Ahi + (size_t)(mb + row) * K + k0 + lkc);
                CP16(ss + S_ALO + so, Alo + (size_t)(mb + row) * K + k0 + lkc);
                CP16(ss + S_W + so,   W   + (size_t)(nb + row) * K + k0 + lkc);
            }
            if (tid < 128) CP4(ss + S_SC + tid * 4, Ws + (size_t)(nb + tid) * nc + (c + NSTAGE - 1));
            CP_COMMIT();
        }

        uint32_t scur = sb + (uint32_t)stage * STAGE_BYTES;
        float gacc[2][4][4];
        #pragma unroll
        for (int a = 0; a < 2; a++)
            #pragma unroll
            for (int b = 0; b < 4; b++)
                #pragma unroll
                for (int d = 0; d < 4; d++) gacc[a][b][d] = 0.f;

        #pragma unroll
        for (int ks = 0; ks < 4; ks++) {
            int kh = ks << 4;
            uint32_t ah[2][4], al[2][4], bfr[2][4];
            #pragma unroll
            for (int mf = 0; mf < 2; mf++) {
                int row = wm * 32 + mf * 16 + (lane & 7) + ((lane >> 3) & 1) * 8;
                int kk = kh + ((lane >> 4) << 3);
                uint32_t so = sw128((uint32_t)(row * 128 + kk * 2));
                LDSM_X4(ah[mf], scur + S_AHI + so);
                LDSM_X4(al[mf], scur + S_ALO + so);
            }
            #pragma unroll
            for (int np = 0; np < 2; np++) {
                int n = wn * 32 + np * 16 + (lane & 7) + ((lane >> 4) << 3);
                int kk = kh + ((lane >> 3) & 1) * 8;
                LDSM_X4(bfr[np], scur + S_W + sw128((uint32_t)(n * 128 + kk * 2)));
            }
            #pragma unroll
            for (int mf = 0; mf < 2; mf++)
                #pragma unroll
                for (int nf = 0; nf < 4; nf++) {
                    uint32_t b0 = bfr[nf >> 1][(nf & 1) * 2], b1 = bfr[nf >> 1][(nf & 1) * 2 + 1];
                    mma_bf16(gacc[mf][nf], ah[mf], b0, b1);
                    mma_bf16(gacc[mf][nf], al[mf], b0, b1);
                }
        }

        const float* sp = reinterpret_cast<const float*>(bp + stage * STAGE_BYTES + S_SC);
        #pragma unroll
        for (int nf = 0; nf < 4; nf++) {
            int cc = wn * 32 + nf * 8 + (lane & 3) * 2;
            float s0 = sp[cc], s1 = sp[cc + 1];
            #pragma unroll
            for (int mf = 0; mf < 2; mf++) {
                acc[mf][nf][0] += gacc[mf][nf][0] * s0;
                acc[mf][nf][1] += gacc[mf][nf][1] * s1;
                acc[mf][nf][2] += gacc[mf][nf][2] * s0;
                acc[mf][nf][3] += gacc[mf][nf][3] * s1;
            }
        }
        if (++stage == NSTAGE) stage = 0;
    }

    #pragma unroll
    for (int mf = 0; mf < 2; mf++) {
        int row = mb + wm * 32 + mf * 16 + (lane >> 2);
        #pragma unroll
        for (int nf = 0; nf < 4; nf++) {
            int col = nb + wn * 32 + nf * 8 + (lane & 3) * 2;
            float v0 = acc[mf][nf][0], v1 = acc[mf][nf][1];
            float v2 = acc[mf][nf][2], v3 = acc[mf][nf][3];
            if (bias) {
                float b0 = bias[col], b1 = bias[col + 1];
                v0 += b0; v1 += b1; v2 += b0; v3 += b1;
            }
            size_t o0 = (size_t)row * O + col;
            size_t o1 = (size_t)(row + 8) * O + col;
            if (res) {
                float2 r0 = *reinterpret_cast<const float2*>(res + o0);
                float2 r1 = *reinterpret_cast<const float2*>(res + o1);
                v0 += r0.x; v1 += r0.y; v2 += r1.x; v3 += r1.y;
            }
            *reinterpret_cast<float2*>(C + o0) = make_float2(v0, v1);
            *reinterpret_cast<float2*>(C + o1) = make_float2(v2, v3);
        }
    }
}

// ---------------- fused RoPE on q (16 heads) + k (4 heads) ----------------
__global__ void rope_all(float* __restrict__ X, const int* __restrict__ offp) {
    int idx = blockIdx.x * blockDim.x + threadIdx.x;
    int total = T_TOK * 20 * 64;
    if (idx >= total) return;
    int j = idx & 63;
    int rest = idx >> 6;
    int h = rest % 20;
    int t = rest / 20;
    int s = t & (SEQ - 1);
    int col = (h < 16) ? h * 128 : 2048 + (h - 16) * 128;
    float pos = (float)(s + *offp);
    float inv = exp2f(-(float)j * (2.0f / 128.0f) * 19.931568569324174f);
    float ang = pos * inv;
    float c, sn;
    sincosf(ang, &sn, &c);
    float* p = X + (size_t)t * 3072 + col + j;
    float x1 = p[0], x2 = p[64];
    p[0]  = x1 * c - x2 * sn;
    p[64] = x2 * c + x1 * sn;
}

// ---------------- smem-tiled flash attention (fp32), reg-double-buffered K/V ----------------
#define ASMEM_BYTES 65536

__global__ void __launch_bounds__(256)
attn_tiled(const float* __restrict__ qkv, __nv_bfloat16* __restrict__ Ohi,
           __nv_bfloat16* __restrict__ Olo) {
    extern __shared__ float asmf[];
    float* q_s = asmf;               // [64][128]
    float* kT  = asmf + 64 * 128;    // [128][32]
    float* v_s = kT + 128 * 32;      // [32][128]

    int tid = threadIdx.x, warp = tid >> 5, lane = tid & 31;
    int Qb = ((int)gridDim.x - 1 - (int)blockIdx.x) * 64;
    int h = blockIdx.y, b = blockIdx.z, kh = h >> 2;
    const float scale = 0.08838834764831843f;

    for (int i = tid; i < 64 * 32; i += 256) {
        int row = i >> 5, c4 = (i & 31) << 2;
        float4 qf = *reinterpret_cast<const float4*>(
            qkv + (size_t)(b * SEQ + Qb + row) * 3072 + h * 128 + c4);
        qf.x *= scale; qf.y *= scale; qf.z *= scale; qf.w *= scale;
        *reinterpret_cast<float4*>(q_s + row * 128 + c4) = qf;
    }

    float m[8], l[8], o[8][4];
    #pragma unroll
    for (int i = 0; i < 8; i++) {
        m[i] = -1e30f; l[i] = 0.f;
        o[i][0] = o[i][1] = o[i][2] = o[i][3] = 0.f;
    }
    int q0 = Qb + warp * 8;
    int nt = (Qb >> 5) + 2;
    int key = tid & 31, dch = tid >> 5;

    // prefetch tile 0 K/V into registers
    float4 kr[4], vr[4];
    {
        const float* kg = qkv + (size_t)(b * SEQ + key) * 3072 + 2048 + kh * 128 + dch * 16;
        const float* vg = kg + 512;
        #pragma unroll
        for (int j = 0; j < 4; j++) {
            kr[j] = *reinterpret_cast<const float4*>(kg + j * 4);
            vr[j] = *reinterpret_cast<const float4*>(vg + j * 4);
        }
    }

    for (int t = 0; t < nt; t++) {
        int kbase = t << 5;
        __syncthreads();    // prior compute done reading kT/v_s (and q_s ready at t=0)
        #pragma unroll
        for (int j = 0; j < 4; j++) {
            int d0 = dch * 16 + j * 4;
            kT[(d0 + 0) * 32 + key] = kr[j].x;
            kT[(d0 + 1) * 32 + key] = kr[j].y;
            kT[(d0 + 2) * 32 + key] = kr[j].z;
            kT[(d0 + 3) * 32 + key] = kr[j].w;
            *reinterpret_cast<float4*>(v_s + key * 128 + d0) = vr[j];
        }
        __syncthreads();

        // prefetch next tile (latency hidden behind compute below)
        if (t + 1 < nt) {
            const float* kg = qkv + (size_t)(b * SEQ + ((t + 1) << 5) + key) * 3072
                              + 2048 + kh * 128 + dch * 16;
            const float* vg = kg + 512;
            #pragma unroll
            for (int j = 0; j < 4; j++) {
                kr[j] = *reinterpret_cast<const float4*>(kg + j * 4);
                vr[j] = *reinterpret_cast<const float4*>(vg + j * 4);
            }
        }

        if (kbase <= q0 + 7) {
            float s[8];
            #pragma unroll
            for (int i = 0; i < 8; i++) s[i] = 0.f;
            #pragma unroll 4
            for (int d = 0; d < 128; d += 4) {
                float k0v = kT[d * 32 + lane],       k1v = kT[(d + 1) * 32 + lane];
                float k2v = kT[(d + 2) * 32 + lane], k3v = kT[(d + 3) * 32 + lane];
                const float* qrow = q_s + warp * 8 * 128 + d;
                #pragma unroll
                for (int qi = 0; qi < 8; qi++) {
                    float4 qf = *reinterpret_cast<const float4*>(qrow + qi * 128);
                    s[qi] += qf.x * k0v + qf.y * k1v + qf.z * k2v + qf.w * k3v;
                }
            }
            int keyg = kbase + lane;
            float p[8];
            #pragma unroll
            for (int qi = 0; qi < 8; qi++) {
                float sv = (keyg <= q0 + qi) ? s[qi] : -1e30f;
                float mx = sv;
                #pragma unroll
                for (int off = 16; off; off >>= 1)
                    mx = fmaxf(mx, __shfl_xor_sync(0xffffffffu, mx, off));
                float mn = fmaxf(m[qi], mx);
                float corr = __expf(m[qi] - mn);
                m[qi] = mn;
                float pv = __expf(sv - mn);
                p[qi] = pv;
                float ps = pv;
                #pragma unroll
                for (int off = 16; off; off >>= 1)
                    ps += __shfl_xor_sync(0xffffffffu, ps, off);
                l[qi] = l[qi] * corr + ps;
                o[qi][0] *= corr; o[qi][1] *= corr; o[qi][2] *= corr; o[qi][3] *= corr;
            }
            #pragma unroll 4
            for (int k = 0; k < 32; k++) {
                float4 vf = *reinterpret_cast<const float4*>(v_s + k * 128 + lane * 4);
                #pragma unroll
                for (int qi = 0; qi < 8; qi++) {
                    float pk = __shfl_sync(0xffffffffu, p[qi], k);
                    o[qi][0] += pk * vf.x; o[qi][1] += pk * vf.y;
                    o[qi][2] += pk * vf.z; o[qi][3] += pk * vf.w;
                }
            }
        }
    }

    #pragma unroll
    for (int qi = 0; qi < 8; qi++) {
        float inv = 1.f / l[qi];
        float vals[4] = { o[qi][0] * inv, o[qi][1] * inv, o[qi][2] * inv, o[qi][3] * inv };
        uint32_t hb[4], lb[4];
        #pragma unroll
        for (int j = 0; j < 4; j++) {
            hb[j] = f2bf_bits(vals[j]);
            lb[j] = f2bf_bits(vals[j] - bf2f(hb[j]));
        }
        size_t base = (size_t)(b * SEQ + q0 + qi) * 2048 + h * 128 + lane * 4;
        *reinterpret_cast<uint2*>(Ohi + base) = make_uint2(hb[0] | (hb[1] << 16), hb[2] | (hb[3] << 16));
        *reinterpret_cast<uint2*>(Olo + base) = make_uint2(lb[0] | (lb[1] << 16), lb[2] | (lb[3] << 16));
    }
}

// ---------------- silu(gate)*up from fused gu, write bf16 hi/lo ----------------
__global__ void silu_mul_split(const float* __restrict__ gu, __nv_bfloat16* __restrict__ hi,
                               __nv_bfloat16* __restrict__ lo) {
    int idx = blockIdx.x * blockDim.x + threadIdx.x;
    if (idx >= T_TOK * 1408) return;
    int row = idx / 1408;
    int c4 = (idx - row * 1408) << 2;
    float4 g = *reinterpret_cast<const float4*>(gu + (size_t)row * 11264 + c4);
    float4 u = *reinterpret_cast<const float4*>(gu + (size_t)row * 11264 + 5632 + c4);
    float vals[4] = {
        (g.x / (1.f + __expf(-g.x))) * u.x,
        (g.y / (1.f + __expf(-g.y))) * u.y,
        (g.z / (1.f + __expf(-g.z))) * u.z,
        (g.w / (1.f + __expf(-g.w))) * u.w };
    uint32_t hb[4], lb[4];
    #pragma unroll
    for (int j = 0; j < 4; j++) {
        hb[j] = f2bf_bits(vals[j]);
        lb[j] = f2bf_bits(vals[j] - bf2f(hb[j]));
    }
    size_t base = (size_t)row * 5632 + c4;
    *reinterpret_cast<uint2*>(hi + base) = make_uint2(hb[0] | (hb[1] << 16), hb[2] | (hb[3] << 16));
    *reinterpret_cast<uint2*>(lo + base) = make_uint2(lb[0] | (lb[1] << 16), lb[2] | (lb[3] << 16));
}

// ---------------- orchestration ----------------
extern "C" void kernel_launch(void* const* d_in, const int* in_sizes, int n_in,
                              void* d_out, int out_size) {
    (void)in_sizes; (void)n_in; (void)out_size;
    const float* x       = (const float*)d_in[0];
    const int*   wq_q    = (const int*)  d_in[1];
    const float* wq_s    = (const float*)d_in[2];
    const float* bq      = (const float*)d_in[3];
    const int*   wk_q    = (const int*)  d_in[4];
    const float* wk_s    = (const float*)d_in[5];
    const float* bk      = (const float*)d_in[6];
    const int*   wv_q    = (const int*)  d_in[7];
    const float* wv_s    = (const float*)d_in[8];
    const float* bv      = (const float*)d_in[9];
    const int*   wo_q    = (const int*)  d_in[10];
    const float* wo_s    = (const float*)d_in[11];
    const int*   gate_q  = (const int*)  d_in[12];
    const float* gate_s  = (const float*)d_in[13];
    const int*   up_q    = (const int*)  d_in[14];
    const float* up_s    = (const float*)d_in[15];
    const int*   down_q  = (const int*)  d_in[16];
    const float* down_s  = (const float*)d_in[17];
    const float* w_in_ln = (const float*)d_in[18];
    const float* w_post_ln = (const float*)d_in[19];
    const int*   offset  = (const int*)  d_in[20];
    float* out = (float*)d_out;

    float *qkv, *x1, *gu, *scales, *biasb;
    __nv_bfloat16 *wbf, *ahi, *alo;
    cudaGetSymbolAddress((void**)&qkv,  g_qkv);
    cudaGetSymbolAddress((void**)&x1,   g_x1);
    cudaGetSymbolAddress((void**)&gu,   g_gu);
    cudaGetSymbolAddress((void**)&wbf,  g_wbf);
    cudaGetSymbolAddress((void**)&ahi,  g_ahi);
    cudaGetSymbolAddress((void**)&alo,  g_alo);
    cudaGetSymbolAddress((void**)&scales, g_scales);
    cudaGetSymbolAddress((void**)&biasb,  g_bias);

    cudaFuncSetAttribute(gemm_mma, cudaFuncAttributeMaxDynamicSharedMemorySize, GSMEM_BYTES);
    cudaFuncSetAttribute(attn_tiled, cudaFuncAttributeMaxDynamicSharedMemorySize, ASMEM_BYTES);

    // scale/bias concat (D2D async copies, graph-safe)
    cudaMemcpyAsync(scales,          wq_s,   65536  * 4, cudaMemcpyDeviceToDevice);
    cudaMemcpyAsync(scales + 65536,  wk_s,   16384  * 4, cudaMemcpyDeviceToDevice);
    cudaMemcpyAsync(scales + 81920,  wv_s,   16384  * 4, cudaMemcpyDeviceToDevice);
    cudaMemcpyAsync(scales + 98304,  gate_s, 180224 * 4, cudaMemcpyDeviceToDevice);
    cudaMemcpyAsync(scales + 278528, up_s,   180224 * 4, cudaMemcpyDeviceToDevice);
    cudaMemcpyAsync(biasb,        bq, 2048 * 4, cudaMemcpyDeviceToDevice);
    cudaMemcpyAsync(biasb + 2048, bk, 512  * 4, cudaMemcpyDeviceToDevice);
    cudaMemcpyAsync(biasb + 2560, bv, 512  * 4, cudaMemcpyDeviceToDevice);

    // all weights -> bf16
    w2bf_all<<<(W_TOTAL / 4 + 255) / 256, 256>>>(wq_q, wk_q, wv_q, wo_q, gate_q, up_q, down_q, wbf);

    // input rmsnorm + split
    rmsnorm_split<<<T_TOK, 256>>>(x, w_in_ln, ahi, alo);

    // fused qkv projection
    gemm_mma<<<dim3(3072 / 128, T_TOK / 128), 512, GSMEM_BYTES>>>(
        ahi, alo, wbf + OFF_QKV, scales, biasb, nullptr, qkv, 3072, D_MODEL);

    // fused RoPE (q + k heads)
    rope_all<<<(T_TOK * 20 * 64 + 255) / 256, 256>>>(qkv, offset);

    // attention -> ahi/alo
    attn_tiled<<<dim3(SEQ / 64, NHEAD, 2), 256, ASMEM_BYTES>>>(qkv, ahi, alo);

    // o-projection + residual -> x1
    gemm_mma<<<dim3(D_MODEL / 128, T_TOK / 128), 512, GSMEM_BYTES>>>(
        ahi, alo, wbf + OFF_WO, wo_s, nullptr, x, x1, D_MODEL, D_MODEL);

    // post rmsnorm + split
    rmsnorm_split<<<T_TOK, 256>>>(x1, w_post_ln, ahi, alo);

    // fused gate|up projection
    gemm_mma<<<dim3(11264 / 128, T_TOK / 128), 512, GSMEM_BYTES>>>(
        ahi, alo, wbf + OFF_GU, scales + 98304, nullptr, nullptr, gu, 11264, D_MODEL);

    // silu(gate)*up + split
    silu_mul_split<<<(T_TOK * 1408 + 255) / 256, 256>>>(gu, ahi, alo);

    // down projection + residual -> out
    gemm_mma<<<dim3(D_MODEL / 128, T_TOK / 128), 512, GSMEM_BYTES>>>(
        ahi, alo, wbf + OFF_DOWN, down_s, nullptr, x1, out, D_MODEL, D_FF);
}